// round 10
// baseline (speedup 1.0000x reference)
#include <cuda_runtime.h>
#include <cuda_fp16.h>
#include <stdint.h>
#include <math.h>

#define MTOT 16384
#define CDIM 512
#define NQKV 1536

// ---------------------------------------------------------------------------
// Scratch (static __device__: no allocations allowed)
// ---------------------------------------------------------------------------
__device__ __half g_x16[MTOT * CDIM];
__device__ __half g_qkv16[(size_t)MTOT * NQKV];
__device__ __half g_s16[MTOT * CDIM];
__device__ __half g_w16[4 * CDIM * CDIM];   // Wq, Wk, Wv, proj

// ---------------------------------------------------------------------------
// PTX helpers (arch-portable)
// ---------------------------------------------------------------------------
__device__ __forceinline__ uint32_t smem_u32(const void* p) {
    uint32_t a;
    asm("{ .reg .u64 t; cvta.to.shared.u64 t, %1; cvt.u32.u64 %0, t; }"
        : "=r"(a) : "l"(p));
    return a;
}
__device__ __forceinline__ void ldm_x4(uint32_t* r, uint32_t addr) {
    asm volatile("ldmatrix.sync.aligned.m8n8.x4.shared.b16 {%0,%1,%2,%3}, [%4];"
                 : "=r"(r[0]), "=r"(r[1]), "=r"(r[2]), "=r"(r[3]) : "r"(addr));
}
__device__ __forceinline__ void mma_f16(float* d, const uint32_t* a, const uint32_t* b) {
    asm volatile(
        "mma.sync.aligned.m16n8k16.row.col.f32.f16.f16.f32 "
        "{%0,%1,%2,%3}, {%4,%5,%6,%7}, {%8,%9}, {%0,%1,%2,%3};"
        : "+f"(d[0]), "+f"(d[1]), "+f"(d[2]), "+f"(d[3])
        : "r"(a[0]), "r"(a[1]), "r"(a[2]), "r"(a[3]), "r"(b[0]), "r"(b[1]));
}
__device__ __forceinline__ void mma_f16_k8(float* d, uint32_t a0, uint32_t a1, uint32_t b0) {
    asm volatile(
        "mma.sync.aligned.m16n8k8.row.col.f32.f16.f16.f32 "
        "{%0,%1,%2,%3}, {%4,%5}, {%6}, {%0,%1,%2,%3};"
        : "+f"(d[0]), "+f"(d[1]), "+f"(d[2]), "+f"(d[3])
        : "r"(a0), "r"(a1), "r"(b0));
}
__device__ __forceinline__ void cp_async16(uint32_t dst, const void* src) {
    asm volatile("cp.async.cg.shared.global [%0], [%1], 16;" :: "r"(dst), "l"(src));
}
#define CP_COMMIT() asm volatile("cp.async.commit_group;" ::: "memory")
#define CP_WAIT(N)  asm volatile("cp.async.wait_group %0;" :: "n"(N) : "memory")

__device__ __forceinline__ uint32_t pack_h2(float a, float b) {
    __half2 h = __floats2half2_rn(a, b);
    return *(uint32_t*)&h;
}

// ---------------------------------------------------------------------------
// fp16 GEMM: BM=128, BN=128, BK=32, 256 threads, 4-stage cp.async, 2 CTAs/SM.
// ---------------------------------------------------------------------------
#define PITCH 40
#define SH ((128 + 128) * PITCH)
#define OFF_B (128 * PITCH)
#define GSMEM (4 * SH * 2)                 // 81920 B

template <bool HOUT>
__global__ __launch_bounds__(256, 2)
void gemm_f16(const __half* __restrict__ A, const __half* __restrict__ B,
              const float* __restrict__ bias, void* __restrict__ Cv, int ldc)
{
    extern __shared__ __align__(16) __half sm[];
    const int tid = threadIdx.x;
    const int wid = tid >> 5, L = tid & 31;
    const int m0 = blockIdx.y * 128;
    const int n0 = blockIdx.x * 128;
    const int wm = (wid >> 2) * 64;
    const int wn = (wid & 3) * 32;
    const uint32_t sb = smem_u32(sm);

    const __half* Ab = A + (size_t)m0 * CDIM;
    const __half* Bb = B + (size_t)n0 * CDIM;

    float acc[4][4][4];
#pragma unroll
    for (int i = 0; i < 4; i++)
#pragma unroll
        for (int j = 0; j < 4; j++)
#pragma unroll
            for (int q = 0; q < 4; q++) acc[i][j][q] = 0.f;

    const int aRow = L & 15, aK = (L >> 4) * 8;
    const int bRowL = (L & 7) + ((L & 16) ? 8 : 0);
    const int bK = ((L >> 3) & 1) * 8;
    const int lr = tid >> 1, lc = tid & 1;

    auto load_stage = [&](int stage, int k0) {
        const uint32_t s0 = sb + (uint32_t)stage * SH * 2;
        cp_async16(s0 + (uint32_t)(lr * PITCH + lc * 8) * 2,
                   Ab + (size_t)lr * CDIM + k0 + lc * 8);
        cp_async16(s0 + (uint32_t)(lr * PITCH + (lc + 2) * 8) * 2,
                   Ab + (size_t)lr * CDIM + k0 + (lc + 2) * 8);
        cp_async16(s0 + OFF_B * 2 + (uint32_t)(lr * PITCH + lc * 8) * 2,
                   Bb + (size_t)lr * CDIM + k0 + lc * 8);
        cp_async16(s0 + OFF_B * 2 + (uint32_t)(lr * PITCH + (lc + 2) * 8) * 2,
                   Bb + (size_t)lr * CDIM + k0 + (lc + 2) * 8);
    };

    load_stage(0, 0);  CP_COMMIT();
    load_stage(1, 32); CP_COMMIT();
    load_stage(2, 64); CP_COMMIT();

    const int NIT = CDIM / 32;   // 16
    for (int s = 0; s < NIT; s++) {
        CP_WAIT(2);
        __syncthreads();
        if (s + 3 < NIT) load_stage((s + 3) & 3, (s + 3) * 32);
        CP_COMMIT();

        const uint32_t pA = sb + (uint32_t)(s & 3) * SH * 2;
        const uint32_t pB = pA + OFF_B * 2;

#pragma unroll
        for (int kk = 0; kk < 32; kk += 16) {
            uint32_t ah[4][4], bh[4][2];
#pragma unroll
            for (int mi = 0; mi < 4; mi++) {
                uint32_t ro = (uint32_t)((wm + mi * 16 + aRow) * PITCH + kk + aK) * 2;
                ldm_x4(ah[mi], pA + ro);
            }
#pragma unroll
            for (int nb = 0; nb < 2; nb++) {
                uint32_t ro = (uint32_t)((wn + nb * 16 + bRowL) * PITCH + kk + bK) * 2;
                uint32_t th[4];
                ldm_x4(th, pB + ro);
                bh[nb * 2][0] = th[0];     bh[nb * 2][1] = th[1];
                bh[nb * 2 + 1][0] = th[2]; bh[nb * 2 + 1][1] = th[3];
            }
#pragma unroll
            for (int mi = 0; mi < 4; mi++)
#pragma unroll
                for (int ni = 0; ni < 4; ni++)
                    mma_f16(acc[mi][ni], ah[mi], bh[ni]);
        }
        __syncthreads();
    }

    const int cr = L >> 2, cc = (L & 3) * 2;
#pragma unroll
    for (int mi = 0; mi < 4; mi++) {
#pragma unroll
        for (int ni = 0; ni < 4; ni++) {
            int row = m0 + wm + mi * 16 + cr;
            int col = n0 + wn + ni * 8 + cc;
            float b0 = 0.f, b1 = 0.f;
            if (bias) { b0 = bias[col]; b1 = bias[col + 1]; }
            if (HOUT) {
                __half* C = (__half*)Cv;
                *(__half2*)&C[(size_t)row * ldc + col] =
                    __floats2half2_rn(acc[mi][ni][0] + b0, acc[mi][ni][1] + b1);
                *(__half2*)&C[(size_t)(row + 8) * ldc + col] =
                    __floats2half2_rn(acc[mi][ni][2] + b0, acc[mi][ni][3] + b1);
            } else {
                float* C = (float*)Cv;
                *(float2*)&C[(size_t)row * ldc + col] =
                    make_float2(acc[mi][ni][0] + b0, acc[mi][ni][1] + b1);
                *(float2*)&C[(size_t)(row + 8) * ldc + col] =
                    make_float2(acc[mi][ni][2] + b0, acc[mi][ni][3] + b1);
            }
        }
    }
}

// ---------------------------------------------------------------------------
// fp32 -> fp16 converts
// ---------------------------------------------------------------------------
__global__ void cvt_x(const float4* __restrict__ src, uint2* __restrict__ dst, int n4)
{
    int i = blockIdx.x * blockDim.x + threadIdx.x;
    if (i >= n4) return;
    float4 v = src[i];
    union { uint2 u; __half b[4]; } H;
    H.b[0] = __float2half(v.x); H.b[1] = __float2half(v.y);
    H.b[2] = __float2half(v.z); H.b[3] = __float2half(v.w);
    dst[i] = H.u;
}

__global__ void cvt_w(const float4* __restrict__ w0, const float4* __restrict__ w1,
                      const float4* __restrict__ w2, const float4* __restrict__ w3,
                      uint2* __restrict__ dst)
{
    int wsel = blockIdx.y;
    const float4* src = (wsel == 0) ? w0 : (wsel == 1) ? w1 : (wsel == 2) ? w2 : w3;
    int i = blockIdx.x * blockDim.x + threadIdx.x;
    float4 v = src[i];
    union { uint2 u; __half b[4]; } H;
    H.b[0] = __float2half(v.x); H.b[1] = __float2half(v.y);
    H.b[2] = __float2half(v.z); H.b[3] = __float2half(v.w);
    dst[(size_t)wsel * 65536 + i] = H.u;
}

// ---------------------------------------------------------------------------
// Per-pixel attention, tensor-core stage2/output, reg-lean (8-block target).
// Gram computed raw first; v-norms come free from its diagonal; softmax
// threads apply the rn_v scaling. Stage-2 scores exp'd+packed per N-tile so
// only 8 fp32 score regs are live. Direct half2 stores in scramble layout.
// ---------------------------------------------------------------------------
#define PQ 68

struct __align__(16) PixS {
    float q[8 * PQ];
    float k[8 * PQ];
    float v[8 * PQ];
    float rn[24];
    float sA[64];
    __align__(16) __half qT[64 * 8];   // q'[e][h]
    __align__(16) __half kT[64 * 8];   // k'[d][h]
    __align__(16) float zpart[2][64];  // per-warp Z partials
    __align__(16) float invb[64];      // 2 / Z_d
};

__global__ __launch_bounds__(128, 8) void attn_kernel(
    const __half* __restrict__ QKV, __half* __restrict__ scr)
{
    __shared__ PixS ps[2];
    const int t = threadIdx.x;
    const int gsel = t >> 6, t6 = t & 63;
    PixS& S = ps[gsel];
    const int pix = blockIdx.x * 2 + gsel;

    // ---- load fp16 qkv -> fp32 padded smem ----
    {
        const uint4* src = (const uint4*)(QKV + (size_t)pix * NQKV);
#pragma unroll
        for (int j = 0; j < 3; j++) {
            int i = j * 64 + t6;
            union { uint4 u; __half h[8]; } U;
            U.u = src[i];
            float* rowp = (j == 0 ? S.q : j == 1 ? S.k : S.v)
                        + (t6 >> 3) * PQ + (t6 & 7) * 8;
            ((float4*)rowp)[0] = make_float4(
                __half2float(U.h[0]), __half2float(U.h[1]),
                __half2float(U.h[2]), __half2float(U.h[3]));
            ((float4*)rowp)[1] = make_float4(
                __half2float(U.h[4]), __half2float(U.h[5]),
                __half2float(U.h[6]), __half2float(U.h[7]));
        }
    }
    __syncthreads();

    // ---- gram of v, RAW (unnormalized); diagonal = ||v_h||^2 ----
    {
        int h = t6 >> 3, g = t6 & 7;
        const float4* ph = (const float4*)(S.v + h * PQ);
        const float4* pg = (const float4*)(S.v + g * PQ);
        float s = 0.f;
#pragma unroll
        for (int i = 0; i < 16; i++) {
            float4 a = ph[i], b = pg[i];
            s = fmaf(a.x, b.x, fmaf(a.y, b.y, fmaf(a.z, b.z, fmaf(a.w, b.w, s))));
        }
        S.sA[t6] = s;
    }
    __syncthreads();

    // ---- norms: q/k by dot (16 threads); v from gram diagonal (8 threads) ----
    if (t6 < 16) {
        int which = t6 >> 3, h = t6 & 7;
        const float* p = (which == 0 ? S.q : S.k) + h * PQ;
        float s = 0.f;
#pragma unroll
        for (int i = 0; i < 16; i++) {
            float4 x = ((const float4*)p)[i];
            s = fmaf(x.x, x.x, fmaf(x.y, x.y, fmaf(x.z, x.z, fmaf(x.w, x.w, s))));
        }
        S.rn[t6] = 1.f / fmaxf(sqrtf(s), 1e-12f);
    } else if (t6 < 24) {
        int h = t6 - 16;
        S.rn[t6] = 1.f / fmaxf(sqrtf(S.sA[h * 9]), 1e-12f);
    }
    __syncthreads();

    // ---- head-mix softmax rows (apply rn_v scaling here; cosines bounded) ----
    if (t6 < 8) {
        float rh = S.rn[16 + t6];
        float e[8], sum = 0.f;
#pragma unroll
        for (int g = 0; g < 8; g++) {
            e[g] = __expf(S.sA[t6 * 8 + g] * rh * S.rn[16 + g]);
            sum += e[g];
        }
        float inv = 1.f / sum;
#pragma unroll
        for (int g = 0; g < 8; g++) S.sA[t6 * 8 + g] = e[g] * inv;
    }
    __syncthreads();

    // ---- head mix at column d = t6: q' -> qT, k' -> kT (both fp16) ----
    {
        const int d = t6;
        float qc[8], kc[8];
#pragma unroll
        for (int g = 0; g < 8; g++) {
            qc[g] = S.q[g * PQ + d] * S.rn[g];
            kc[g] = S.k[g * PQ + d] * S.rn[8 + g];
        }
        union { uint4 u; __half hh[8]; } QP, KP;
#pragma unroll
        for (int h = 0; h < 8; h++) {
            float s1 = 0.f, s2 = 0.f;
#pragma unroll
            for (int g = 0; g < 8; g++) {
                s1 = fmaf(S.sA[h * 8 + g], qc[g], s1);
                s2 = fmaf(S.sA[h * 8 + g], kc[g], s2);
            }
            QP.hh[h] = __float2half(s1);
            KP.hh[h] = __float2half(s2);
        }
        *(uint4*)(S.qT + d * 8) = QP.u;
        *(uint4*)(S.kT + d * 8) = KP.u;
    }
    __syncthreads();

    // ================= tensor-core phase =================
    const int w = (t >> 5) & 1;
    const int L = t & 31;
    const int g = L >> 2, tq = L & 3;

    uint32_t qa[4];
    ldm_x4(qa, smem_u32(S.qT) + (uint32_t)(w * 32 + L) * 16);
    uint32_t kb[8];
    ldm_x4(kb + 0, smem_u32(S.kT) + (uint32_t)L * 16);
    ldm_x4(kb + 4, smem_u32(S.kT) + (uint32_t)(32 + L) * 16);

    // stage-2 mma per N-tile: mma -> exp -> pack (only 8 score regs live)
    uint32_t eh[2][8][2];
    float pzlo[8], pzhi[8];
#pragma unroll
    for (int nj = 0; nj < 8; nj++) {
        float c0[4] = {0.f, 0.f, 0.f, 0.f};
        float c1[4] = {0.f, 0.f, 0.f, 0.f};
        mma_f16_k8(c0, qa[0], qa[1], kb[nj]);
        mma_f16_k8(c1, qa[2], qa[3], kb[nj]);
        float e00 = __expf(c0[0]), e01 = __expf(c0[1]);
        float e02 = __expf(c0[2]), e03 = __expf(c0[3]);
        float e10 = __expf(c1[0]), e11 = __expf(c1[1]);
        float e12 = __expf(c1[2]), e13 = __expf(c1[3]);
        pzlo[nj] = e00 + e02 + e10 + e12;
        pzhi[nj] = e01 + e03 + e11 + e13;
        eh[0][nj][0] = pack_h2(e00, e01);
        eh[0][nj][1] = pack_h2(e02, e03);
        eh[1][nj][0] = pack_h2(e10, e11);
        eh[1][nj][1] = pack_h2(e12, e13);
    }
    // reduce Z over g (lanes differing in bits 2..4)
#pragma unroll
    for (int nj = 0; nj < 8; nj++) {
#pragma unroll
        for (int m = 4; m <= 16; m <<= 1) {
            pzlo[nj] += __shfl_xor_sync(0xffffffffu, pzlo[nj], m);
            pzhi[nj] += __shfl_xor_sync(0xffffffffu, pzhi[nj], m);
        }
    }
    if (g == 0) {
#pragma unroll
        for (int nj = 0; nj < 8; nj++)
            *(float2*)(S.zpart[w] + nj * 8 + 2 * tq) = make_float2(pzlo[nj], pzhi[nj]);
    }
    __syncthreads();

    S.invb[t6] = 2.f / (S.zpart[0][t6] + S.zpart[1][t6]);
    __syncthreads();

    // output mma: out^T(e,h) = P^T @ vhat
    float Co[2][4];
    Co[0][0] = Co[0][1] = Co[0][2] = Co[0][3] = 0.f;
    Co[1][0] = Co[1][1] = Co[1][2] = Co[1][3] = 0.f;
#pragma unroll
    for (int kj = 0; kj < 4; kj++) {
        uint32_t bv[2];
        {
            int d0 = 16 * kj + 2 * tq;
            float2 v0 = *(const float2*)(S.v + g * PQ + d0);
            float2 i0 = *(const float2*)(S.invb + d0);
            bv[0] = pack_h2(v0.x * i0.x, v0.y * i0.y);
            float2 v1 = *(const float2*)(S.v + g * PQ + d0 + 8);
            float2 i1 = *(const float2*)(S.invb + d0 + 8);
            bv[1] = pack_h2(v1.x * i1.x, v1.y * i1.y);
        }
#pragma unroll
        for (int mi = 0; mi < 2; mi++) {
            uint32_t av[4] = { eh[mi][2 * kj][0], eh[mi][2 * kj][1],
                               eh[mi][2 * kj + 1][0], eh[mi][2 * kj + 1][1] };
            mma_f16(Co[mi], av, bv);
        }
    }

    // store: scr[b, e*64 + n/64, (n%64)*8 + h]
    {
        const int b = pix >> 12;
        const int n = pix & 4095;
        const size_t base = ((size_t)(b * 4096 + (n >> 6))) * CDIM + (n & 63) * 8 + 2 * tq;
        const size_t estep = (size_t)64 * CDIM;
#pragma unroll
        for (int mi = 0; mi < 2; mi++) {
            int e = w * 32 + mi * 16 + g;
            *(__half2*)(scr + base + (size_t)e * estep) =
                __floats2half2_rn(Co[mi][0], Co[mi][1]);
            *(__half2*)(scr + base + (size_t)(e + 8) * estep) =
                __floats2half2_rn(Co[mi][2], Co[mi][3]);
        }
    }
}

// ---------------------------------------------------------------------------
extern "C" void kernel_launch(void* const* d_in, const int* in_sizes, int n_in,
                              void* d_out, int out_size)
{
    const float* x     = (const float*)d_in[0];
    const float* Wq    = (const float*)d_in[1];
    const float* Wk    = (const float*)d_in[2];
    const float* Wv    = (const float*)d_in[3];
    // d_in[4] = conv_w: dead in the reference
    const float* projw = (const float*)d_in[5];
    const float* projb = (const float*)d_in[6];
    float* out = (float*)d_out;

    cudaFuncSetAttribute(gemm_f16<true>, cudaFuncAttributeMaxDynamicSharedMemorySize, GSMEM);
    cudaFuncSetAttribute(gemm_f16<false>, cudaFuncAttributeMaxDynamicSharedMemorySize, GSMEM);

    __half *x16, *s16, *w16, *qkv16;
    cudaGetSymbolAddress((void**)&x16, g_x16);
    cudaGetSymbolAddress((void**)&s16, g_s16);
    cudaGetSymbolAddress((void**)&w16, g_w16);
    cudaGetSymbolAddress((void**)&qkv16, g_qkv16);

    cvt_x<<<MTOT * CDIM / 4 / 256, 256>>>((const float4*)x, (uint2*)x16, MTOT * CDIM / 4);
    cvt_w<<<dim3(256, 4), 256>>>(
        (const float4*)Wq, (const float4*)Wk, (const float4*)Wv,
        (const float4*)projw, (uint2*)w16);

    // fused QKV GEMM: [16384,512] x [1536,512]^T -> fp16 [16384,1536]
    gemm_f16<true><<<dim3(NQKV / 128, MTOT / 128), 256, GSMEM>>>(
        x16, w16, nullptr, qkv16, NQKV);

    attn_kernel<<<MTOT / 2, 128>>>(qkv16, s16);

    // proj GEMM: [16384,512] x [512,512]^T -> fp32 out
    gemm_f16<false><<<dim3(CDIM / 128, MTOT / 128), 256, GSMEM>>>(
        s16, w16 + 3 * CDIM * CDIM, projb, out, CDIM);
}

// round 11
// speedup vs baseline: 1.0497x; 1.0497x over previous
#include <cuda_runtime.h>
#include <cuda_fp16.h>
#include <stdint.h>
#include <math.h>

#define MTOT 16384
#define CDIM 512
#define NQKV 1536

// ---------------------------------------------------------------------------
// Scratch (static __device__: no allocations allowed)
// ---------------------------------------------------------------------------
__device__ __half g_x16[MTOT * CDIM];
__device__ __half g_qkv16[(size_t)MTOT * NQKV];
__device__ __half g_s16[MTOT * CDIM];
__device__ __half g_w16[4 * CDIM * CDIM];   // Wq, Wk, Wv, proj

// ---------------------------------------------------------------------------
// PTX helpers (arch-portable)
// ---------------------------------------------------------------------------
__device__ __forceinline__ uint32_t smem_u32(const void* p) {
    uint32_t a;
    asm("{ .reg .u64 t; cvta.to.shared.u64 t, %1; cvt.u32.u64 %0, t; }"
        : "=r"(a) : "l"(p));
    return a;
}
__device__ __forceinline__ void ldm_x4(uint32_t* r, uint32_t addr) {
    asm volatile("ldmatrix.sync.aligned.m8n8.x4.shared.b16 {%0,%1,%2,%3}, [%4];"
                 : "=r"(r[0]), "=r"(r[1]), "=r"(r[2]), "=r"(r[3]) : "r"(addr));
}
__device__ __forceinline__ void mma_f16(float* d, const uint32_t* a, const uint32_t* b) {
    asm volatile(
        "mma.sync.aligned.m16n8k16.row.col.f32.f16.f16.f32 "
        "{%0,%1,%2,%3}, {%4,%5,%6,%7}, {%8,%9}, {%0,%1,%2,%3};"
        : "+f"(d[0]), "+f"(d[1]), "+f"(d[2]), "+f"(d[3])
        : "r"(a[0]), "r"(a[1]), "r"(a[2]), "r"(a[3]), "r"(b[0]), "r"(b[1]));
}
__device__ __forceinline__ void mma_f16_k8(float* d, uint32_t a0, uint32_t a1, uint32_t b0) {
    asm volatile(
        "mma.sync.aligned.m16n8k8.row.col.f32.f16.f16.f32 "
        "{%0,%1,%2,%3}, {%4,%5}, {%6}, {%0,%1,%2,%3};"
        : "+f"(d[0]), "+f"(d[1]), "+f"(d[2]), "+f"(d[3])
        : "r"(a0), "r"(a1), "r"(b0));
}
__device__ __forceinline__ void cp_async16(uint32_t dst, const void* src) {
    asm volatile("cp.async.cg.shared.global [%0], [%1], 16;" :: "r"(dst), "l"(src));
}
#define CP_COMMIT() asm volatile("cp.async.commit_group;" ::: "memory")
#define CP_WAIT(N)  asm volatile("cp.async.wait_group %0;" :: "n"(N) : "memory")

// group-local barrier: 64 threads (2 warps) of pixel-group gsel
#define NB(gsel) asm volatile("bar.sync %0, 64;" :: "r"(1 + (gsel)) : "memory")

__device__ __forceinline__ uint32_t pack_h2(float a, float b) {
    __half2 h = __floats2half2_rn(a, b);
    return *(uint32_t*)&h;
}

// ---------------------------------------------------------------------------
// fp16 GEMM: BM=128, BN=128, BK=32, 256 threads, 3-stage cp.async, 2 CTAs/SM.
// Single barrier per mainloop iteration (post-wait); trailing sync removed —
// entering iter s+1 implies all threads finished reading stage s%3, which is
// exactly the stage the new cp.async writes.
// ---------------------------------------------------------------------------
#define PITCH 40
#define SH ((128 + 128) * PITCH)
#define OFF_B (128 * PITCH)
#define GSMEM (3 * SH * 2)                 // 61440 B

template <bool HOUT>
__global__ __launch_bounds__(256, 2)
void gemm_f16(const __half* __restrict__ A, const __half* __restrict__ B,
              const float* __restrict__ bias, void* __restrict__ Cv, int ldc)
{
    extern __shared__ __align__(16) __half sm[];
    const int tid = threadIdx.x;
    const int wid = tid >> 5, L = tid & 31;
    const int m0 = blockIdx.y * 128;
    const int n0 = blockIdx.x * 128;
    const int wm = (wid >> 2) * 64;
    const int wn = (wid & 3) * 32;
    const uint32_t sb = smem_u32(sm);

    const __half* Ab = A + (size_t)m0 * CDIM;
    const __half* Bb = B + (size_t)n0 * CDIM;

    float acc[4][4][4];
#pragma unroll
    for (int i = 0; i < 4; i++)
#pragma unroll
        for (int j = 0; j < 4; j++)
#pragma unroll
            for (int q = 0; q < 4; q++) acc[i][j][q] = 0.f;

    const int aRow = L & 15, aK = (L >> 4) * 8;
    const int bRowL = (L & 7) + ((L & 16) ? 8 : 0);
    const int bK = ((L >> 3) & 1) * 8;
    const int lr = tid >> 1, lc = tid & 1;

    auto load_stage = [&](int stage, int k0) {
        const uint32_t s0 = sb + (uint32_t)stage * SH * 2;
        cp_async16(s0 + (uint32_t)(lr * PITCH + lc * 8) * 2,
                   Ab + (size_t)lr * CDIM + k0 + lc * 8);
        cp_async16(s0 + (uint32_t)(lr * PITCH + (lc + 2) * 8) * 2,
                   Ab + (size_t)lr * CDIM + k0 + (lc + 2) * 8);
        cp_async16(s0 + OFF_B * 2 + (uint32_t)(lr * PITCH + lc * 8) * 2,
                   Bb + (size_t)lr * CDIM + k0 + lc * 8);
        cp_async16(s0 + OFF_B * 2 + (uint32_t)(lr * PITCH + (lc + 2) * 8) * 2,
                   Bb + (size_t)lr * CDIM + k0 + (lc + 2) * 8);
    };

    load_stage(0, 0);  CP_COMMIT();
    load_stage(1, 32); CP_COMMIT();

    const int NIT = CDIM / 32;   // 16
    for (int s = 0; s < NIT; s++) {
        CP_WAIT(1);
        __syncthreads();
        if (s + 2 < NIT) load_stage((s + 2) % 3, (s + 2) * 32);
        CP_COMMIT();

        const uint32_t pA = sb + (uint32_t)(s % 3) * SH * 2;
        const uint32_t pB = pA + OFF_B * 2;

#pragma unroll
        for (int kk = 0; kk < 32; kk += 16) {
            uint32_t ah[4][4], bh[4][2];
#pragma unroll
            for (int mi = 0; mi < 4; mi++) {
                uint32_t ro = (uint32_t)((wm + mi * 16 + aRow) * PITCH + kk + aK) * 2;
                ldm_x4(ah[mi], pA + ro);
            }
#pragma unroll
            for (int nb = 0; nb < 2; nb++) {
                uint32_t ro = (uint32_t)((wn + nb * 16 + bRowL) * PITCH + kk + bK) * 2;
                uint32_t th[4];
                ldm_x4(th, pB + ro);
                bh[nb * 2][0] = th[0];     bh[nb * 2][1] = th[1];
                bh[nb * 2 + 1][0] = th[2]; bh[nb * 2 + 1][1] = th[3];
            }
#pragma unroll
            for (int mi = 0; mi < 4; mi++)
#pragma unroll
                for (int ni = 0; ni < 4; ni++)
                    mma_f16(acc[mi][ni], ah[mi], bh[ni]);
        }
    }

    const int cr = L >> 2, cc = (L & 3) * 2;
#pragma unroll
    for (int mi = 0; mi < 4; mi++) {
#pragma unroll
        for (int ni = 0; ni < 4; ni++) {
            int row = m0 + wm + mi * 16 + cr;
            int col = n0 + wn + ni * 8 + cc;
            float b0 = 0.f, b1 = 0.f;
            if (bias) { b0 = bias[col]; b1 = bias[col + 1]; }
            if (HOUT) {
                __half* C = (__half*)Cv;
                *(__half2*)&C[(size_t)row * ldc + col] =
                    __floats2half2_rn(acc[mi][ni][0] + b0, acc[mi][ni][1] + b1);
                *(__half2*)&C[(size_t)(row + 8) * ldc + col] =
                    __floats2half2_rn(acc[mi][ni][2] + b0, acc[mi][ni][3] + b1);
            } else {
                float* C = (float*)Cv;
                *(float2*)&C[(size_t)row * ldc + col] =
                    make_float2(acc[mi][ni][0] + b0, acc[mi][ni][1] + b1);
                *(float2*)&C[(size_t)(row + 8) * ldc + col] =
                    make_float2(acc[mi][ni][2] + b0, acc[mi][ni][3] + b1);
            }
        }
    }
}

// ---------------------------------------------------------------------------
// fp32 -> fp16 converts
// ---------------------------------------------------------------------------
__global__ void cvt_x(const float4* __restrict__ src, uint2* __restrict__ dst, int n4)
{
    int i = blockIdx.x * blockDim.x + threadIdx.x;
    if (i >= n4) return;
    float4 v = src[i];
    union { uint2 u; __half b[4]; } H;
    H.b[0] = __float2half(v.x); H.b[1] = __float2half(v.y);
    H.b[2] = __float2half(v.z); H.b[3] = __float2half(v.w);
    dst[i] = H.u;
}

__global__ void cvt_w(const float4* __restrict__ w0, const float4* __restrict__ w1,
                      const float4* __restrict__ w2, const float4* __restrict__ w3,
                      uint2* __restrict__ dst)
{
    int wsel = blockIdx.y;
    const float4* src = (wsel == 0) ? w0 : (wsel == 1) ? w1 : (wsel == 2) ? w2 : w3;
    int i = blockIdx.x * blockDim.x + threadIdx.x;
    float4 v = src[i];
    union { uint2 u; __half b[4]; } H;
    H.b[0] = __float2half(v.x); H.b[1] = __float2half(v.y);
    H.b[2] = __float2half(v.z); H.b[3] = __float2half(v.w);
    dst[(size_t)wsel * 65536 + i] = H.u;
}

// ---------------------------------------------------------------------------
// Per-pixel attention (R9 structure), with per-pixel-group NAMED barriers:
// all shared state is group-local (ps[gsel]), so the two pixels in a block
// no longer serialize each other's phases at block-wide __syncthreads.
// ---------------------------------------------------------------------------
#define PQ 68

struct __align__(16) PixS {
    float q[8 * PQ];
    float k[8 * PQ];
    float v[8 * PQ];
    float rn[24];
    float sA[64];
    __align__(16) __half qT[64 * 8];   // q'[e][h]
    __align__(16) __half kT[64 * 8];   // k'[d][h]
    __align__(16) float zpart[2][64];  // per-warp Z partials
    __align__(16) float invb[64];      // 2 / Z_d
};

__global__ __launch_bounds__(128) void attn_kernel(
    const __half* __restrict__ QKV, __half* __restrict__ scr)
{
    __shared__ PixS ps[2];
    const int t = threadIdx.x;
    const int gsel = t >> 6, t6 = t & 63;
    PixS& S = ps[gsel];
    const int pix = blockIdx.x * 2 + gsel;

    // ---- load fp16 qkv -> fp32 padded smem ----
    {
        const uint4* src = (const uint4*)(QKV + (size_t)pix * NQKV);
#pragma unroll
        for (int j = 0; j < 3; j++) {
            int i = j * 64 + t6;
            union { uint4 u; __half h[8]; } U;
            U.u = src[i];
            float* rowp = (j == 0 ? S.q : j == 1 ? S.k : S.v)
                        + (t6 >> 3) * PQ + (t6 & 7) * 8;
            ((float4*)rowp)[0] = make_float4(
                __half2float(U.h[0]), __half2float(U.h[1]),
                __half2float(U.h[2]), __half2float(U.h[3]));
            ((float4*)rowp)[1] = make_float4(
                __half2float(U.h[4]), __half2float(U.h[5]),
                __half2float(U.h[6]), __half2float(U.h[7]));
        }
    }
    NB(gsel);

    // ---- inverse norms ----
    if (t6 < 24) {
        int which = t6 >> 3, h = t6 & 7;
        const float* p = (which == 0 ? S.q : which == 1 ? S.k : S.v) + h * PQ;
        float s = 0.f;
#pragma unroll
        for (int i = 0; i < 16; i++) {
            float4 x = ((const float4*)p)[i];
            s = fmaf(x.x, x.x, fmaf(x.y, x.y, fmaf(x.z, x.z, fmaf(x.w, x.w, s))));
        }
        S.rn[t6] = 1.f / fmaxf(sqrtf(s), 1e-12f);
    }
    NB(gsel);

    // ---- gram of normalized v ----
    {
        int h = t6 >> 3, g = t6 & 7;
        const float4* ph = (const float4*)(S.v + h * PQ);
        const float4* pg = (const float4*)(S.v + g * PQ);
        float s = 0.f;
#pragma unroll
        for (int i = 0; i < 16; i++) {
            float4 a = ph[i], b = pg[i];
            s = fmaf(a.x, b.x, fmaf(a.y, b.y, fmaf(a.z, b.z, fmaf(a.w, b.w, s))));
        }
        S.sA[t6] = s * S.rn[16 + h] * S.rn[16 + g];
    }
    NB(gsel);

    // ---- head-mix softmax rows (cosines bounded, no max needed) ----
    if (t6 < 8) {
        float e[8], sum = 0.f;
#pragma unroll
        for (int g = 0; g < 8; g++) { e[g] = __expf(S.sA[t6 * 8 + g]); sum += e[g]; }
        float inv = 1.f / sum;
#pragma unroll
        for (int g = 0; g < 8; g++) S.sA[t6 * 8 + g] = e[g] * inv;
    }
    NB(gsel);

    // ---- head mix at column d = t6: q' -> qT, k' -> kT (both fp16) ----
    {
        const int d = t6;
        float qc[8], kc[8];
#pragma unroll
        for (int g = 0; g < 8; g++) {
            qc[g] = S.q[g * PQ + d] * S.rn[g];
            kc[g] = S.k[g * PQ + d] * S.rn[8 + g];
        }
        union { uint4 u; __half hh[8]; } QP, KP;
#pragma unroll
        for (int h = 0; h < 8; h++) {
            float s1 = 0.f, s2 = 0.f;
#pragma unroll
            for (int g = 0; g < 8; g++) {
                s1 = fmaf(S.sA[h * 8 + g], qc[g], s1);
                s2 = fmaf(S.sA[h * 8 + g], kc[g], s2);
            }
            QP.hh[h] = __float2half(s1);
            KP.hh[h] = __float2half(s2);
        }
        *(uint4*)(S.qT + d * 8) = QP.u;
        *(uint4*)(S.kT + d * 8) = KP.u;
    }
    NB(gsel);

    // ================= tensor-core phase =================
    const int w = (t >> 5) & 1;       // warp-in-pixel
    const int L = t & 31;
    const int g = L >> 2, tq = L & 3;

    uint32_t qa[4];
    ldm_x4(qa, smem_u32(S.qT) + (uint32_t)(w * 32 + L) * 16);
    uint32_t kb[8];
    ldm_x4(kb + 0, smem_u32(S.kT) + (uint32_t)L * 16);
    ldm_x4(kb + 4, smem_u32(S.kT) + (uint32_t)(32 + L) * 16);

    // Stage-2 mma: 2 M-tiles x 8 N-tiles, K=8 (all mmas first: ILP)
    float Cs[2][8][4];
#pragma unroll
    for (int mi = 0; mi < 2; mi++)
#pragma unroll
        for (int nj = 0; nj < 8; nj++) {
            Cs[mi][nj][0] = Cs[mi][nj][1] = Cs[mi][nj][2] = Cs[mi][nj][3] = 0.f;
            mma_f16_k8(Cs[mi][nj], qa[2 * mi], qa[2 * mi + 1], kb[nj]);
        }

    // exp + Z partials + pack to A-fragments of the output mma
    uint32_t eh[2][8][2];
    float pzlo[8], pzhi[8];
#pragma unroll
    for (int nj = 0; nj < 8; nj++) { pzlo[nj] = 0.f; pzhi[nj] = 0.f; }
#pragma unroll
    for (int mi = 0; mi < 2; mi++)
#pragma unroll
        for (int nj = 0; nj < 8; nj++) {
            float e0 = __expf(Cs[mi][nj][0]);
            float e1 = __expf(Cs[mi][nj][1]);
            float e2 = __expf(Cs[mi][nj][2]);
            float e3 = __expf(Cs[mi][nj][3]);
            pzlo[nj] += e0 + e2;
            pzhi[nj] += e1 + e3;
            eh[mi][nj][0] = pack_h2(e0, e1);
            eh[mi][nj][1] = pack_h2(e2, e3);
        }
    // reduce Z over g (lanes differing in bits 2..4)
#pragma unroll
    for (int nj = 0; nj < 8; nj++) {
#pragma unroll
        for (int m = 4; m <= 16; m <<= 1) {
            pzlo[nj] += __shfl_xor_sync(0xffffffffu, pzlo[nj], m);
            pzhi[nj] += __shfl_xor_sync(0xffffffffu, pzhi[nj], m);
        }
    }
    if (g == 0) {
#pragma unroll
        for (int nj = 0; nj < 8; nj++)
            *(float2*)(S.zpart[w] + nj * 8 + 2 * tq) = make_float2(pzlo[nj], pzhi[nj]);
    }
    NB(gsel);

    // invb[d] = 2 / (zA + zB)   (v+v doubling folded here)
    S.invb[t6] = 2.f / (S.zpart[0][t6] + S.zpart[1][t6]);
    NB(gsel);

    // Output mma: out^T(e,h) = P^T @ vhat, M-tiles 2, N=8, K-tiles 4 (k16)
    float Co[2][4];
    Co[0][0] = Co[0][1] = Co[0][2] = Co[0][3] = 0.f;
    Co[1][0] = Co[1][1] = Co[1][2] = Co[1][3] = 0.f;
#pragma unroll
    for (int kj = 0; kj < 4; kj++) {
        uint32_t bv[2];
        {
            int d0 = 16 * kj + 2 * tq;
            float2 v0 = *(const float2*)(S.v + g * PQ + d0);
            float2 i0 = *(const float2*)(S.invb + d0);
            bv[0] = pack_h2(v0.x * i0.x, v0.y * i0.y);
            float2 v1 = *(const float2*)(S.v + g * PQ + d0 + 8);
            float2 i1 = *(const float2*)(S.invb + d0 + 8);
            bv[1] = pack_h2(v1.x * i1.x, v1.y * i1.y);
        }
#pragma unroll
        for (int mi = 0; mi < 2; mi++) {
            uint32_t av[4] = { eh[mi][2 * kj][0], eh[mi][2 * kj][1],
                               eh[mi][2 * kj + 1][0], eh[mi][2 * kj + 1][1] };
            mma_f16(Co[mi], av, bv);
        }
    }

    // store: scr[b, e*64 + n/64, (n%64)*8 + h], half2 per (e, h-pair)
    {
        const int b = pix >> 12;
        const int n = pix & 4095;
        const size_t base = ((size_t)(b * 4096 + (n >> 6))) * CDIM + (n & 63) * 8 + 2 * tq;
        const size_t estep = (size_t)64 * CDIM;
#pragma unroll
        for (int mi = 0; mi < 2; mi++) {
            int e = w * 32 + mi * 16 + g;
            *(__half2*)(scr + base + (size_t)e * estep) =
                __floats2half2_rn(Co[mi][0], Co[mi][1]);
            *(__half2*)(scr + base + (size_t)(e + 8) * estep) =
                __floats2half2_rn(Co[mi][2], Co[mi][3]);
        }
    }
}

// ---------------------------------------------------------------------------
extern "C" void kernel_launch(void* const* d_in, const int* in_sizes, int n_in,
                              void* d_out, int out_size)
{
    const float* x     = (const float*)d_in[0];
    const float* Wq    = (const float*)d_in[1];
    const float* Wk    = (const float*)d_in[2];
    const float* Wv    = (const float*)d_in[3];
    // d_in[4] = conv_w: dead in the reference
    const float* projw = (const float*)d_in[5];
    const float* projb = (const float*)d_in[6];
    float* out = (float*)d_out;

    cudaFuncSetAttribute(gemm_f16<true>, cudaFuncAttributeMaxDynamicSharedMemorySize, GSMEM);
    cudaFuncSetAttribute(gemm_f16<false>, cudaFuncAttributeMaxDynamicSharedMemorySize, GSMEM);

    __half *x16, *s16, *w16, *qkv16;
    cudaGetSymbolAddress((void**)&x16, g_x16);
    cudaGetSymbolAddress((void**)&s16, g_s16);
    cudaGetSymbolAddress((void**)&w16, g_w16);
    cudaGetSymbolAddress((void**)&qkv16, g_qkv16);

    cvt_x<<<MTOT * CDIM / 4 / 256, 256>>>((const float4*)x, (uint2*)x16, MTOT * CDIM / 4);
    cvt_w<<<dim3(256, 4), 256>>>(
        (const float4*)Wq, (const float4*)Wk, (const float4*)Wv,
        (const float4*)projw, (uint2*)w16);

    // fused QKV GEMM: [16384,512] x [1536,512]^T -> fp16 [16384,1536]
    gemm_f16<true><<<dim3(NQKV / 128, MTOT / 128), 256, GSMEM>>>(
        x16, w16, nullptr, qkv16, NQKV);

    attn_kernel<<<MTOT / 2, 128>>>(qkv16, s16);

    // proj GEMM: [16384,512] x [512,512]^T -> fp32 out
    gemm_f16<false><<<dim3(CDIM / 128, MTOT / 128), 256, GSMEM>>>(
        s16, w16 + 3 * CDIM * CDIM, projb, out, CDIM);
}

// round 12
// speedup vs baseline: 1.0757x; 1.0247x over previous
#include <cuda_runtime.h>
#include <cuda_fp16.h>
#include <stdint.h>
#include <math.h>

#define MTOT 16384
#define CDIM 512
#define NQKV 1536

// ---------------------------------------------------------------------------
// Scratch (static __device__: no allocations allowed)
// ---------------------------------------------------------------------------
__device__ __half g_x16[MTOT * CDIM];
__device__ __half g_qkv16[(size_t)MTOT * NQKV];
__device__ __half g_s16[MTOT * CDIM];
__device__ __half g_w16[4 * CDIM * CDIM];   // Wq, Wk, Wv, proj

// ---------------------------------------------------------------------------
// PTX helpers (arch-portable)
// ---------------------------------------------------------------------------
__device__ __forceinline__ uint32_t smem_u32(const void* p) {
    uint32_t a;
    asm("{ .reg .u64 t; cvta.to.shared.u64 t, %1; cvt.u32.u64 %0, t; }"
        : "=r"(a) : "l"(p));
    return a;
}
__device__ __forceinline__ void ldm_x4(uint32_t* r, uint32_t addr) {
    asm volatile("ldmatrix.sync.aligned.m8n8.x4.shared.b16 {%0,%1,%2,%3}, [%4];"
                 : "=r"(r[0]), "=r"(r[1]), "=r"(r[2]), "=r"(r[3]) : "r"(addr));
}
__device__ __forceinline__ void mma_f16(float* d, const uint32_t* a, const uint32_t* b) {
    asm volatile(
        "mma.sync.aligned.m16n8k16.row.col.f32.f16.f16.f32 "
        "{%0,%1,%2,%3}, {%4,%5,%6,%7}, {%8,%9}, {%0,%1,%2,%3};"
        : "+f"(d[0]), "+f"(d[1]), "+f"(d[2]), "+f"(d[3])
        : "r"(a[0]), "r"(a[1]), "r"(a[2]), "r"(a[3]), "r"(b[0]), "r"(b[1]));
}
__device__ __forceinline__ void mma_f16_k8(float* d, uint32_t a0, uint32_t a1, uint32_t b0) {
    asm volatile(
        "mma.sync.aligned.m16n8k8.row.col.f32.f16.f16.f32 "
        "{%0,%1,%2,%3}, {%4,%5}, {%6}, {%0,%1,%2,%3};"
        : "+f"(d[0]), "+f"(d[1]), "+f"(d[2]), "+f"(d[3])
        : "r"(a0), "r"(a1), "r"(b0));
}
__device__ __forceinline__ void cp_async16(uint32_t dst, const void* src) {
    asm volatile("cp.async.cg.shared.global [%0], [%1], 16;" :: "r"(dst), "l"(src));
}
#define CP_COMMIT() asm volatile("cp.async.commit_group;" ::: "memory")
#define CP_WAIT(N)  asm volatile("cp.async.wait_group %0;" :: "n"(N) : "memory")

__device__ __forceinline__ uint32_t pack_h2(float a, float b) {
    __half2 h = __floats2half2_rn(a, b);
    return *(uint32_t*)&h;
}

// ---------------------------------------------------------------------------
// fp16 GEMM: BM=128, BN=128, BK=32, 256 threads, 3-stage cp.async, 2 CTAs/SM.
// Single barrier per mainloop iteration (post-wait).
// ---------------------------------------------------------------------------
#define PITCH 40
#define SH ((128 + 128) * PITCH)
#define OFF_B (128 * PITCH)
#define GSMEM (3 * SH * 2)                 // 61440 B

template <bool HOUT>
__global__ __launch_bounds__(256, 2)
void gemm_f16(const __half* __restrict__ A, const __half* __restrict__ B,
              const float* __restrict__ bias, void* __restrict__ Cv, int ldc)
{
    extern __shared__ __align__(16) __half sm[];
    const int tid = threadIdx.x;
    const int wid = tid >> 5, L = tid & 31;
    const int m0 = blockIdx.y * 128;
    const int n0 = blockIdx.x * 128;
    const int wm = (wid >> 2) * 64;
    const int wn = (wid & 3) * 32;
    const uint32_t sb = smem_u32(sm);

    const __half* Ab = A + (size_t)m0 * CDIM;
    const __half* Bb = B + (size_t)n0 * CDIM;

    float acc[4][4][4];
#pragma unroll
    for (int i = 0; i < 4; i++)
#pragma unroll
        for (int j = 0; j < 4; j++)
#pragma unroll
            for (int q = 0; q < 4; q++) acc[i][j][q] = 0.f;

    const int aRow = L & 15, aK = (L >> 4) * 8;
    const int bRowL = (L & 7) + ((L & 16) ? 8 : 0);
    const int bK = ((L >> 3) & 1) * 8;
    const int lr = tid >> 1, lc = tid & 1;

    auto load_stage = [&](int stage, int k0) {
        const uint32_t s0 = sb + (uint32_t)stage * SH * 2;
        cp_async16(s0 + (uint32_t)(lr * PITCH + lc * 8) * 2,
                   Ab + (size_t)lr * CDIM + k0 + lc * 8);
        cp_async16(s0 + (uint32_t)(lr * PITCH + (lc + 2) * 8) * 2,
                   Ab + (size_t)lr * CDIM + k0 + (lc + 2) * 8);
        cp_async16(s0 + OFF_B * 2 + (uint32_t)(lr * PITCH + lc * 8) * 2,
                   Bb + (size_t)lr * CDIM + k0 + lc * 8);
        cp_async16(s0 + OFF_B * 2 + (uint32_t)(lr * PITCH + (lc + 2) * 8) * 2,
                   Bb + (size_t)lr * CDIM + k0 + (lc + 2) * 8);
    };

    load_stage(0, 0);  CP_COMMIT();
    load_stage(1, 32); CP_COMMIT();

    const int NIT = CDIM / 32;   // 16
    for (int s = 0; s < NIT; s++) {
        CP_WAIT(1);
        __syncthreads();
        if (s + 2 < NIT) load_stage((s + 2) % 3, (s + 2) * 32);
        CP_COMMIT();

        const uint32_t pA = sb + (uint32_t)(s % 3) * SH * 2;
        const uint32_t pB = pA + OFF_B * 2;

#pragma unroll
        for (int kk = 0; kk < 32; kk += 16) {
            uint32_t ah[4][4], bh[4][2];
#pragma unroll
            for (int mi = 0; mi < 4; mi++) {
                uint32_t ro = (uint32_t)((wm + mi * 16 + aRow) * PITCH + kk + aK) * 2;
                ldm_x4(ah[mi], pA + ro);
            }
#pragma unroll
            for (int nb = 0; nb < 2; nb++) {
                uint32_t ro = (uint32_t)((wn + nb * 16 + bRowL) * PITCH + kk + bK) * 2;
                uint32_t th[4];
                ldm_x4(th, pB + ro);
                bh[nb * 2][0] = th[0];     bh[nb * 2][1] = th[1];
                bh[nb * 2 + 1][0] = th[2]; bh[nb * 2 + 1][1] = th[3];
            }
#pragma unroll
            for (int mi = 0; mi < 4; mi++)
#pragma unroll
                for (int ni = 0; ni < 4; ni++)
                    mma_f16(acc[mi][ni], ah[mi], bh[ni]);
        }
    }

    const int cr = L >> 2, cc = (L & 3) * 2;
#pragma unroll
    for (int mi = 0; mi < 4; mi++) {
#pragma unroll
        for (int ni = 0; ni < 4; ni++) {
            int row = m0 + wm + mi * 16 + cr;
            int col = n0 + wn + ni * 8 + cc;
            float b0 = 0.f, b1 = 0.f;
            if (bias) { b0 = bias[col]; b1 = bias[col + 1]; }
            if (HOUT) {
                __half* C = (__half*)Cv;
                *(__half2*)&C[(size_t)row * ldc + col] =
                    __floats2half2_rn(acc[mi][ni][0] + b0, acc[mi][ni][1] + b1);
                *(__half2*)&C[(size_t)(row + 8) * ldc + col] =
                    __floats2half2_rn(acc[mi][ni][2] + b0, acc[mi][ni][3] + b1);
            } else {
                float* C = (float*)Cv;
                *(float2*)&C[(size_t)row * ldc + col] =
                    make_float2(acc[mi][ni][0] + b0, acc[mi][ni][1] + b1);
                *(float2*)&C[(size_t)(row + 8) * ldc + col] =
                    make_float2(acc[mi][ni][2] + b0, acc[mi][ni][3] + b1);
            }
        }
    }
}

// ---------------------------------------------------------------------------
// fp32 -> fp16 converts
// ---------------------------------------------------------------------------
__global__ void cvt_x(const float4* __restrict__ src, uint2* __restrict__ dst, int n4)
{
    int i = blockIdx.x * blockDim.x + threadIdx.x;
    if (i >= n4) return;
    float4 v = src[i];
    union { uint2 u; __half b[4]; } H;
    H.b[0] = __float2half(v.x); H.b[1] = __float2half(v.y);
    H.b[2] = __float2half(v.z); H.b[3] = __float2half(v.w);
    dst[i] = H.u;
}

__global__ void cvt_w(const float4* __restrict__ w0, const float4* __restrict__ w1,
                      const float4* __restrict__ w2, const float4* __restrict__ w3,
                      uint2* __restrict__ dst)
{
    int wsel = blockIdx.y;
    const float4* src = (wsel == 0) ? w0 : (wsel == 1) ? w1 : (wsel == 2) ? w2 : w3;
    int i = blockIdx.x * blockDim.x + threadIdx.x;
    float4 v = src[i];
    union { uint2 u; __half b[4]; } H;
    H.b[0] = __float2half(v.x); H.b[1] = __float2half(v.y);
    H.b[2] = __float2half(v.z); H.b[3] = __float2half(v.w);
    dst[(size_t)wsel * 65536 + i] = H.u;
}

// ---------------------------------------------------------------------------
// Per-pixel attention (R9 body), ONE pixel per 64-thread block:
// __syncthreads is now a 2-warp barrier — per-pixel phase decoupling without
// named-barrier asm or its register cost.
// ---------------------------------------------------------------------------
#define PQ 68

struct __align__(16) PixS {
    float q[8 * PQ];
    float k[8 * PQ];
    float v[8 * PQ];
    float rn[24];
    float sA[64];
    __align__(16) __half qT[64 * 8];   // q'[e][h]
    __align__(16) __half kT[64 * 8];   // k'[d][h]
    __align__(16) float zpart[2][64];  // per-warp Z partials
    __align__(16) float invb[64];      // 2 / Z_d
};

__global__ __launch_bounds__(64) void attn_kernel(
    const __half* __restrict__ QKV, __half* __restrict__ scr)
{
    __shared__ PixS S;
    const int t6 = threadIdx.x;        // 0..63
    const int pix = blockIdx.x;

    // ---- load fp16 qkv -> fp32 padded smem ----
    {
        const uint4* src = (const uint4*)(QKV + (size_t)pix * NQKV);
#pragma unroll
        for (int j = 0; j < 3; j++) {
            int i = j * 64 + t6;
            union { uint4 u; __half h[8]; } U;
            U.u = src[i];
            float* rowp = (j == 0 ? S.q : j == 1 ? S.k : S.v)
                        + (t6 >> 3) * PQ + (t6 & 7) * 8;
            ((float4*)rowp)[0] = make_float4(
                __half2float(U.h[0]), __half2float(U.h[1]),
                __half2float(U.h[2]), __half2float(U.h[3]));
            ((float4*)rowp)[1] = make_float4(
                __half2float(U.h[4]), __half2float(U.h[5]),
                __half2float(U.h[6]), __half2float(U.h[7]));
        }
    }
    __syncthreads();

    // ---- inverse norms ----
    if (t6 < 24) {
        int which = t6 >> 3, h = t6 & 7;
        const float* p = (which == 0 ? S.q : which == 1 ? S.k : S.v) + h * PQ;
        float s = 0.f;
#pragma unroll
        for (int i = 0; i < 16; i++) {
            float4 x = ((const float4*)p)[i];
            s = fmaf(x.x, x.x, fmaf(x.y, x.y, fmaf(x.z, x.z, fmaf(x.w, x.w, s))));
        }
        S.rn[t6] = 1.f / fmaxf(sqrtf(s), 1e-12f);
    }
    __syncthreads();

    // ---- gram of normalized v ----
    {
        int h = t6 >> 3, g = t6 & 7;
        const float4* ph = (const float4*)(S.v + h * PQ);
        const float4* pg = (const float4*)(S.v + g * PQ);
        float s = 0.f;
#pragma unroll
        for (int i = 0; i < 16; i++) {
            float4 a = ph[i], b = pg[i];
            s = fmaf(a.x, b.x, fmaf(a.y, b.y, fmaf(a.z, b.z, fmaf(a.w, b.w, s))));
        }
        S.sA[t6] = s * S.rn[16 + h] * S.rn[16 + g];
    }
    __syncthreads();

    // ---- head-mix softmax rows (cosines bounded, no max needed) ----
    if (t6 < 8) {
        float e[8], sum = 0.f;
#pragma unroll
        for (int g = 0; g < 8; g++) { e[g] = __expf(S.sA[t6 * 8 + g]); sum += e[g]; }
        float inv = 1.f / sum;
#pragma unroll
        for (int g = 0; g < 8; g++) S.sA[t6 * 8 + g] = e[g] * inv;
    }
    __syncthreads();

    // ---- head mix at column d = t6: q' -> qT, k' -> kT (both fp16) ----
    {
        const int d = t6;
        float qc[8], kc[8];
#pragma unroll
        for (int g = 0; g < 8; g++) {
            qc[g] = S.q[g * PQ + d] * S.rn[g];
            kc[g] = S.k[g * PQ + d] * S.rn[8 + g];
        }
        union { uint4 u; __half hh[8]; } QP, KP;
#pragma unroll
        for (int h = 0; h < 8; h++) {
            float s1 = 0.f, s2 = 0.f;
#pragma unroll
            for (int g = 0; g < 8; g++) {
                s1 = fmaf(S.sA[h * 8 + g], qc[g], s1);
                s2 = fmaf(S.sA[h * 8 + g], kc[g], s2);
            }
            QP.hh[h] = __float2half(s1);
            KP.hh[h] = __float2half(s2);
        }
        *(uint4*)(S.qT + d * 8) = QP.u;
        *(uint4*)(S.kT + d * 8) = KP.u;
    }
    __syncthreads();

    // ================= tensor-core phase =================
    const int w = t6 >> 5;            // warp-in-pixel (0/1)
    const int L = t6 & 31;
    const int g = L >> 2, tq = L & 3;

    uint32_t qa[4];
    ldm_x4(qa, smem_u32(S.qT) + (uint32_t)(w * 32 + L) * 16);
    uint32_t kb[8];
    ldm_x4(kb + 0, smem_u32(S.kT) + (uint32_t)L * 16);
    ldm_x4(kb + 4, smem_u32(S.kT) + (uint32_t)(32 + L) * 16);

    // Stage-2 mma: 2 M-tiles x 8 N-tiles, K=8 (all mmas first: ILP)
    float Cs[2][8][4];
#pragma unroll
    for (int mi = 0; mi < 2; mi++)
#pragma unroll
        for (int nj = 0; nj < 8; nj++) {
            Cs[mi][nj][0] = Cs[mi][nj][1] = Cs[mi][nj][2] = Cs[mi][nj][3] = 0.f;
            mma_f16_k8(Cs[mi][nj], qa[2 * mi], qa[2 * mi + 1], kb[nj]);
        }

    // exp + Z partials + pack to A-fragments of the output mma
    uint32_t eh[2][8][2];
    float pzlo[8], pzhi[8];
#pragma unroll
    for (int nj = 0; nj < 8; nj++) { pzlo[nj] = 0.f; pzhi[nj] = 0.f; }
#pragma unroll
    for (int mi = 0; mi < 2; mi++)
#pragma unroll
        for (int nj = 0; nj < 8; nj++) {
            float e0 = __expf(Cs[mi][nj][0]);
            float e1 = __expf(Cs[mi][nj][1]);
            float e2 = __expf(Cs[mi][nj][2]);
            float e3 = __expf(Cs[mi][nj][3]);
            pzlo[nj] += e0 + e2;
            pzhi[nj] += e1 + e3;
            eh[mi][nj][0] = pack_h2(e0, e1);
            eh[mi][nj][1] = pack_h2(e2, e3);
        }
    // reduce Z over g (lanes differing in bits 2..4)
#pragma unroll
    for (int nj = 0; nj < 8; nj++) {
#pragma unroll
        for (int m = 4; m <= 16; m <<= 1) {
            pzlo[nj] += __shfl_xor_sync(0xffffffffu, pzlo[nj], m);
            pzhi[nj] += __shfl_xor_sync(0xffffffffu, pzhi[nj], m);
        }
    }
    if (g == 0) {
#pragma unroll
        for (int nj = 0; nj < 8; nj++)
            *(float2*)(S.zpart[w] + nj * 8 + 2 * tq) = make_float2(pzlo[nj], pzhi[nj]);
    }
    __syncthreads();

    // invb[d] = 2 / (zA + zB)   (v+v doubling folded here)
    S.invb[t6] = 2.f / (S.zpart[0][t6] + S.zpart[1][t6]);
    __syncthreads();

    // Output mma: out^T(e,h) = P^T @ vhat, M-tiles 2, N=8, K-tiles 4 (k16)
    float Co[2][4];
    Co[0][0] = Co[0][1] = Co[0][2] = Co[0][3] = 0.f;
    Co[1][0] = Co[1][1] = Co[1][2] = Co[1][3] = 0.f;
#pragma unroll
    for (int kj = 0; kj < 4; kj++) {
        uint32_t bv[2];
        {
            int d0 = 16 * kj + 2 * tq;
            float2 v0 = *(const float2*)(S.v + g * PQ + d0);
            float2 i0 = *(const float2*)(S.invb + d0);
            bv[0] = pack_h2(v0.x * i0.x, v0.y * i0.y);
            float2 v1 = *(const float2*)(S.v + g * PQ + d0 + 8);
            float2 i1 = *(const float2*)(S.invb + d0 + 8);
            bv[1] = pack_h2(v1.x * i1.x, v1.y * i1.y);
        }
#pragma unroll
        for (int mi = 0; mi < 2; mi++) {
            uint32_t av[4] = { eh[mi][2 * kj][0], eh[mi][2 * kj][1],
                               eh[mi][2 * kj + 1][0], eh[mi][2 * kj + 1][1] };
            mma_f16(Co[mi], av, bv);
        }
    }

    // store: scr[b, e*64 + n/64, (n%64)*8 + h], half2 per (e, h-pair)
    {
        const int b = pix >> 12;
        const int n = pix & 4095;
        const size_t base = ((size_t)(b * 4096 + (n >> 6))) * CDIM + (n & 63) * 8 + 2 * tq;
        const size_t estep = (size_t)64 * CDIM;
#pragma unroll
        for (int mi = 0; mi < 2; mi++) {
            int e = w * 32 + mi * 16 + g;
            *(__half2*)(scr + base + (size_t)e * estep) =
                __floats2half2_rn(Co[mi][0], Co[mi][1]);
            *(__half2*)(scr + base + (size_t)(e + 8) * estep) =
                __floats2half2_rn(Co[mi][2], Co[mi][3]);
        }
    }
}

// ---------------------------------------------------------------------------
extern "C" void kernel_launch(void* const* d_in, const int* in_sizes, int n_in,
                              void* d_out, int out_size)
{
    const float* x     = (const float*)d_in[0];
    const float* Wq    = (const float*)d_in[1];
    const float* Wk    = (const float*)d_in[2];
    const float* Wv    = (const float*)d_in[3];
    // d_in[4] = conv_w: dead in the reference
    const float* projw = (const float*)d_in[5];
    const float* projb = (const float*)d_in[6];
    float* out = (float*)d_out;

    cudaFuncSetAttribute(gemm_f16<true>, cudaFuncAttributeMaxDynamicSharedMemorySize, GSMEM);
    cudaFuncSetAttribute(gemm_f16<false>, cudaFuncAttributeMaxDynamicSharedMemorySize, GSMEM);

    __half *x16, *s16, *w16, *qkv16;
    cudaGetSymbolAddress((void**)&x16, g_x16);
    cudaGetSymbolAddress((void**)&s16, g_s16);
    cudaGetSymbolAddress((void**)&w16, g_w16);
    cudaGetSymbolAddress((void**)&qkv16, g_qkv16);

    cvt_x<<<MTOT * CDIM / 4 / 256, 256>>>((const float4*)x, (uint2*)x16, MTOT * CDIM / 4);
    cvt_w<<<dim3(256, 4), 256>>>(
        (const float4*)Wq, (const float4*)Wk, (const float4*)Wv,
        (const float4*)projw, (uint2*)w16);

    // fused QKV GEMM: [16384,512] x [1536,512]^T -> fp16 [16384,1536]
    gemm_f16<true><<<dim3(NQKV / 128, MTOT / 128), 256, GSMEM>>>(
        x16, w16, nullptr, qkv16, NQKV);

    attn_kernel<<<MTOT, 64>>>(qkv16, s16);

    // proj GEMM: [16384,512] x [512,512]^T -> fp32 out
    gemm_f16<false><<<dim3(CDIM / 128, MTOT / 128), 256, GSMEM>>>(
        s16, w16 + 3 * CDIM * CDIM, projb, out, CDIM);
}

// round 13
// speedup vs baseline: 1.0874x; 1.0109x over previous
#include <cuda_runtime.h>
#include <cuda_fp16.h>
#include <stdint.h>
#include <math.h>

#define MTOT 16384
#define CDIM 512
#define NQKV 1536
#define LOG2E 1.44269504088896f

// ---------------------------------------------------------------------------
// Scratch (static __device__: no allocations allowed)
// ---------------------------------------------------------------------------
__device__ __half g_x16[MTOT * CDIM];
__device__ __half g_qkv16[(size_t)MTOT * NQKV];
__device__ __half g_s16[MTOT * CDIM];
__device__ __half g_w16[4 * CDIM * CDIM];   // Wq, Wk, Wv, proj

// ---------------------------------------------------------------------------
// PTX helpers (arch-portable)
// ---------------------------------------------------------------------------
__device__ __forceinline__ uint32_t smem_u32(const void* p) {
    uint32_t a;
    asm("{ .reg .u64 t; cvta.to.shared.u64 t, %1; cvt.u32.u64 %0, t; }"
        : "=r"(a) : "l"(p));
    return a;
}
__device__ __forceinline__ void ldm_x4(uint32_t* r, uint32_t addr) {
    asm volatile("ldmatrix.sync.aligned.m8n8.x4.shared.b16 {%0,%1,%2,%3}, [%4];"
                 : "=r"(r[0]), "=r"(r[1]), "=r"(r[2]), "=r"(r[3]) : "r"(addr));
}
__device__ __forceinline__ void mma_f16(float* d, const uint32_t* a, const uint32_t* b) {
    asm volatile(
        "mma.sync.aligned.m16n8k16.row.col.f32.f16.f16.f32 "
        "{%0,%1,%2,%3}, {%4,%5,%6,%7}, {%8,%9}, {%0,%1,%2,%3};"
        : "+f"(d[0]), "+f"(d[1]), "+f"(d[2]), "+f"(d[3])
        : "r"(a[0]), "r"(a[1]), "r"(a[2]), "r"(a[3]), "r"(b[0]), "r"(b[1]));
}
__device__ __forceinline__ void mma_f16_k8(float* d, uint32_t a0, uint32_t a1, uint32_t b0) {
    asm volatile(
        "mma.sync.aligned.m16n8k8.row.col.f32.f16.f16.f32 "
        "{%0,%1,%2,%3}, {%4,%5}, {%6}, {%0,%1,%2,%3};"
        : "+f"(d[0]), "+f"(d[1]), "+f"(d[2]), "+f"(d[3])
        : "r"(a0), "r"(a1), "r"(b0));
}
__device__ __forceinline__ void cp_async16(uint32_t dst, const void* src) {
    asm volatile("cp.async.cg.shared.global [%0], [%1], 16;" :: "r"(dst), "l"(src));
}
#define CP_COMMIT() asm volatile("cp.async.commit_group;" ::: "memory")
#define CP_WAIT(N)  asm volatile("cp.async.wait_group %0;" :: "n"(N) : "memory")

__device__ __forceinline__ uint32_t pack_h2(float a, float b) {
    __half2 h = __floats2half2_rn(a, b);
    return *(uint32_t*)&h;
}
__device__ __forceinline__ float ex2f(float x) {
    float r;
    asm("ex2.approx.f32 %0, %1;" : "=f"(r) : "f"(x));
    return r;
}

// ---------------------------------------------------------------------------
// fp16 GEMM: BM=128, BN=128, BK=32, 256 threads, 3-stage cp.async, 2 CTAs/SM.
// Single barrier per mainloop iteration (post-wait).
// ---------------------------------------------------------------------------
#define PITCH 40
#define SH ((128 + 128) * PITCH)
#define OFF_B (128 * PITCH)
#define GSMEM (3 * SH * 2)                 // 61440 B

template <bool HOUT>
__global__ __launch_bounds__(256, 2)
void gemm_f16(const __half* __restrict__ A, const __half* __restrict__ B,
              const float* __restrict__ bias, void* __restrict__ Cv, int ldc)
{
    extern __shared__ __align__(16) __half sm[];
    const int tid = threadIdx.x;
    const int wid = tid >> 5, L = tid & 31;
    const int m0 = blockIdx.y * 128;
    const int n0 = blockIdx.x * 128;
    const int wm = (wid >> 2) * 64;
    const int wn = (wid & 3) * 32;
    const uint32_t sb = smem_u32(sm);

    const __half* Ab = A + (size_t)m0 * CDIM;
    const __half* Bb = B + (size_t)n0 * CDIM;

    float acc[4][4][4];
#pragma unroll
    for (int i = 0; i < 4; i++)
#pragma unroll
        for (int j = 0; j < 4; j++)
#pragma unroll
            for (int q = 0; q < 4; q++) acc[i][j][q] = 0.f;

    const int aRow = L & 15, aK = (L >> 4) * 8;
    const int bRowL = (L & 7) + ((L & 16) ? 8 : 0);
    const int bK = ((L >> 3) & 1) * 8;
    const int lr = tid >> 1, lc = tid & 1;

    auto load_stage = [&](int stage, int k0) {
        const uint32_t s0 = sb + (uint32_t)stage * SH * 2;
        cp_async16(s0 + (uint32_t)(lr * PITCH + lc * 8) * 2,
                   Ab + (size_t)lr * CDIM + k0 + lc * 8);
        cp_async16(s0 + (uint32_t)(lr * PITCH + (lc + 2) * 8) * 2,
                   Ab + (size_t)lr * CDIM + k0 + (lc + 2) * 8);
        cp_async16(s0 + OFF_B * 2 + (uint32_t)(lr * PITCH + lc * 8) * 2,
                   Bb + (size_t)lr * CDIM + k0 + lc * 8);
        cp_async16(s0 + OFF_B * 2 + (uint32_t)(lr * PITCH + (lc + 2) * 8) * 2,
                   Bb + (size_t)lr * CDIM + k0 + (lc + 2) * 8);
    };

    load_stage(0, 0);  CP_COMMIT();
    load_stage(1, 32); CP_COMMIT();

    const int NIT = CDIM / 32;   // 16
    for (int s = 0; s < NIT; s++) {
        CP_WAIT(1);
        __syncthreads();
        if (s + 2 < NIT) load_stage((s + 2) % 3, (s + 2) * 32);
        CP_COMMIT();

        const uint32_t pA = sb + (uint32_t)(s % 3) * SH * 2;
        const uint32_t pB = pA + OFF_B * 2;

#pragma unroll
        for (int kk = 0; kk < 32; kk += 16) {
            uint32_t ah[4][4], bh[4][2];
#pragma unroll
            for (int mi = 0; mi < 4; mi++) {
                uint32_t ro = (uint32_t)((wm + mi * 16 + aRow) * PITCH + kk + aK) * 2;
                ldm_x4(ah[mi], pA + ro);
            }
#pragma unroll
            for (int nb = 0; nb < 2; nb++) {
                uint32_t ro = (uint32_t)((wn + nb * 16 + bRowL) * PITCH + kk + bK) * 2;
                uint32_t th[4];
                ldm_x4(th, pB + ro);
                bh[nb * 2][0] = th[0];     bh[nb * 2][1] = th[1];
                bh[nb * 2 + 1][0] = th[2]; bh[nb * 2 + 1][1] = th[3];
            }
#pragma unroll
            for (int mi = 0; mi < 4; mi++)
#pragma unroll
                for (int ni = 0; ni < 4; ni++)
                    mma_f16(acc[mi][ni], ah[mi], bh[ni]);
        }
    }

    const int cr = L >> 2, cc = (L & 3) * 2;
#pragma unroll
    for (int mi = 0; mi < 4; mi++) {
#pragma unroll
        for (int ni = 0; ni < 4; ni++) {
            int row = m0 + wm + mi * 16 + cr;
            int col = n0 + wn + ni * 8 + cc;
            float b0 = 0.f, b1 = 0.f;
            if (bias) { b0 = bias[col]; b1 = bias[col + 1]; }
            if (HOUT) {
                __half* C = (__half*)Cv;
                *(__half2*)&C[(size_t)row * ldc + col] =
                    __floats2half2_rn(acc[mi][ni][0] + b0, acc[mi][ni][1] + b1);
                *(__half2*)&C[(size_t)(row + 8) * ldc + col] =
                    __floats2half2_rn(acc[mi][ni][2] + b0, acc[mi][ni][3] + b1);
            } else {
                float* C = (float*)Cv;
                *(float2*)&C[(size_t)row * ldc + col] =
                    make_float2(acc[mi][ni][0] + b0, acc[mi][ni][1] + b1);
                *(float2*)&C[(size_t)(row + 8) * ldc + col] =
                    make_float2(acc[mi][ni][2] + b0, acc[mi][ni][3] + b1);
            }
        }
    }
}

// ---------------------------------------------------------------------------
// fp32 -> fp16 converts. cvt_x: 4 elements/thread, loads batched (MLP=4).
// ---------------------------------------------------------------------------
__global__ void cvt_x(const float4* __restrict__ src, uint2* __restrict__ dst, int n4)
{
    int i = blockIdx.x * blockDim.x + threadIdx.x;
    int stride = gridDim.x * blockDim.x;
    float4 v0 = src[i];
    float4 v1 = src[i + stride];
    float4 v2 = src[i + 2 * stride];
    float4 v3 = src[i + 3 * stride];
    union { uint2 u; __half b[4]; } H;
#define CVT4(V, IDX) \
    H.b[0] = __float2half(V.x); H.b[1] = __float2half(V.y); \
    H.b[2] = __float2half(V.z); H.b[3] = __float2half(V.w); \
    dst[IDX] = H.u;
    CVT4(v0, i)
    CVT4(v1, i + stride)
    CVT4(v2, i + 2 * stride)
    CVT4(v3, i + 3 * stride)
#undef CVT4
}

__global__ void cvt_w(const float4* __restrict__ w0, const float4* __restrict__ w1,
                      const float4* __restrict__ w2, const float4* __restrict__ w3,
                      uint2* __restrict__ dst)
{
    int wsel = blockIdx.y;
    const float4* src = (wsel == 0) ? w0 : (wsel == 1) ? w1 : (wsel == 2) ? w2 : w3;
    int i = blockIdx.x * blockDim.x + threadIdx.x;
    float4 v = src[i];
    union { uint2 u; __half b[4]; } H;
    H.b[0] = __float2half(v.x); H.b[1] = __float2half(v.y);
    H.b[2] = __float2half(v.z); H.b[3] = __float2half(v.w);
    dst[(size_t)wsel * 65536 + i] = H.u;
}

// ---------------------------------------------------------------------------
// Per-pixel attention (R12 body), issue-count cuts:
// - head-mix reads sA rows via 2x LDS.128 per h (was 8x scalar LDS)
// - rn_k stored pre-scaled by log2(e): stage-2 scores are log2-domain, exp
//   becomes bare ex2.approx (no per-exp FMUL). Bit-path otherwise identical.
// ---------------------------------------------------------------------------
#define PQ 68

struct __align__(16) PixS {
    float q[8 * PQ];
    float k[8 * PQ];
    float v[8 * PQ];
    float rn[24];
    float sA[64];
    __align__(16) __half qT[64 * 8];   // q'[e][h]
    __align__(16) __half kT[64 * 8];   // k'[d][h], scaled by log2e
    __align__(16) float zpart[2][64];  // per-warp Z partials
    __align__(16) float invb[64];      // 2 / Z_d
};

__global__ __launch_bounds__(64) void attn_kernel(
    const __half* __restrict__ QKV, __half* __restrict__ scr)
{
    __shared__ PixS S;
    const int t6 = threadIdx.x;        // 0..63
    const int pix = blockIdx.x;

    // ---- load fp16 qkv -> fp32 padded smem ----
    {
        const uint4* src = (const uint4*)(QKV + (size_t)pix * NQKV);
#pragma unroll
        for (int j = 0; j < 3; j++) {
            int i = j * 64 + t6;
            union { uint4 u; __half h[8]; } U;
            U.u = src[i];
            float* rowp = (j == 0 ? S.q : j == 1 ? S.k : S.v)
                        + (t6 >> 3) * PQ + (t6 & 7) * 8;
            ((float4*)rowp)[0] = make_float4(
                __half2float(U.h[0]), __half2float(U.h[1]),
                __half2float(U.h[2]), __half2float(U.h[3]));
            ((float4*)rowp)[1] = make_float4(
                __half2float(U.h[4]), __half2float(U.h[5]),
                __half2float(U.h[6]), __half2float(U.h[7]));
        }
    }
    __syncthreads();

    // ---- inverse norms (k's pre-scaled by log2e for the ex2 fast path) ----
    if (t6 < 24) {
        int which = t6 >> 3, h = t6 & 7;
        const float* p = (which == 0 ? S.q : which == 1 ? S.k : S.v) + h * PQ;
        float s = 0.f;
#pragma unroll
        for (int i = 0; i < 16; i++) {
            float4 x = ((const float4*)p)[i];
            s = fmaf(x.x, x.x, fmaf(x.y, x.y, fmaf(x.z, x.z, fmaf(x.w, x.w, s))));
        }
        float inv = 1.f / fmaxf(sqrtf(s), 1e-12f);
        S.rn[t6] = (which == 1) ? inv * LOG2E : inv;
    }
    __syncthreads();

    // ---- gram of normalized v ----
    {
        int h = t6 >> 3, g = t6 & 7;
        const float4* ph = (const float4*)(S.v + h * PQ);
        const float4* pg = (const float4*)(S.v + g * PQ);
        float s = 0.f;
#pragma unroll
        for (int i = 0; i < 16; i++) {
            float4 a = ph[i], b = pg[i];
            s = fmaf(a.x, b.x, fmaf(a.y, b.y, fmaf(a.z, b.z, fmaf(a.w, b.w, s))));
        }
        S.sA[t6] = s * S.rn[16 + h] * S.rn[16 + g];
    }
    __syncthreads();

    // ---- head-mix softmax rows (cosines bounded, no max needed) ----
    if (t6 < 8) {
        float e[8], sum = 0.f;
#pragma unroll
        for (int g = 0; g < 8; g++) { e[g] = __expf(S.sA[t6 * 8 + g]); sum += e[g]; }
        float inv = 1.f / sum;
#pragma unroll
        for (int g = 0; g < 8; g++) S.sA[t6 * 8 + g] = e[g] * inv;
    }
    __syncthreads();

    // ---- head mix at column d = t6: q' -> qT, k'(log2-scaled) -> kT ----
    {
        const int d = t6;
        float qc[8], kc[8];
#pragma unroll
        for (int g = 0; g < 8; g++) {
            qc[g] = S.q[g * PQ + d] * S.rn[g];
            kc[g] = S.k[g * PQ + d] * S.rn[8 + g];   // includes log2e
        }
        union { uint4 u; __half hh[8]; } QP, KP;
#pragma unroll
        for (int h = 0; h < 8; h++) {
            float4 a0 = *(const float4*)&S.sA[h * 8];
            float4 a1 = *(const float4*)&S.sA[h * 8 + 4];
            float s1 = a0.x * qc[0];
            s1 = fmaf(a0.y, qc[1], s1);
            s1 = fmaf(a0.z, qc[2], s1);
            s1 = fmaf(a0.w, qc[3], s1);
            s1 = fmaf(a1.x, qc[4], s1);
            s1 = fmaf(a1.y, qc[5], s1);
            s1 = fmaf(a1.z, qc[6], s1);
            s1 = fmaf(a1.w, qc[7], s1);
            float s2 = a0.x * kc[0];
            s2 = fmaf(a0.y, kc[1], s2);
            s2 = fmaf(a0.z, kc[2], s2);
            s2 = fmaf(a0.w, kc[3], s2);
            s2 = fmaf(a1.x, kc[4], s2);
            s2 = fmaf(a1.y, kc[5], s2);
            s2 = fmaf(a1.z, kc[6], s2);
            s2 = fmaf(a1.w, kc[7], s2);
            QP.hh[h] = __float2half(s1);
            KP.hh[h] = __float2half(s2);
        }
        *(uint4*)(S.qT + d * 8) = QP.u;
        *(uint4*)(S.kT + d * 8) = KP.u;
    }
    __syncthreads();

    // ================= tensor-core phase =================
    const int w = t6 >> 5;            // warp-in-pixel (0/1)
    const int L = t6 & 31;
    const int g = L >> 2, tq = L & 3;

    uint32_t qa[4];
    ldm_x4(qa, smem_u32(S.qT) + (uint32_t)(w * 32 + L) * 16);
    uint32_t kb[8];
    ldm_x4(kb + 0, smem_u32(S.kT) + (uint32_t)L * 16);
    ldm_x4(kb + 4, smem_u32(S.kT) + (uint32_t)(32 + L) * 16);

    // Stage-2 mma: 2 M-tiles x 8 N-tiles, K=8 (all mmas first: ILP)
    float Cs[2][8][4];
#pragma unroll
    for (int mi = 0; mi < 2; mi++)
#pragma unroll
        for (int nj = 0; nj < 8; nj++) {
            Cs[mi][nj][0] = Cs[mi][nj][1] = Cs[mi][nj][2] = Cs[mi][nj][3] = 0.f;
            mma_f16_k8(Cs[mi][nj], qa[2 * mi], qa[2 * mi + 1], kb[nj]);
        }

    // ex2 (scores already log2-domain) + Z partials + pack to A-fragments
    uint32_t eh[2][8][2];
    float pzlo[8], pzhi[8];
#pragma unroll
    for (int nj = 0; nj < 8; nj++) { pzlo[nj] = 0.f; pzhi[nj] = 0.f; }
#pragma unroll
    for (int mi = 0; mi < 2; mi++)
#pragma unroll
        for (int nj = 0; nj < 8; nj++) {
            float e0 = ex2f(Cs[mi][nj][0]);
            float e1 = ex2f(Cs[mi][nj][1]);
            float e2 = ex2f(Cs[mi][nj][2]);
            float e3 = ex2f(Cs[mi][nj][3]);
            pzlo[nj] += e0 + e2;
            pzhi[nj] += e1 + e3;
            eh[mi][nj][0] = pack_h2(e0, e1);
            eh[mi][nj][1] = pack_h2(e2, e3);
        }
    // reduce Z over g (lanes differing in bits 2..4)
#pragma unroll
    for (int nj = 0; nj < 8; nj++) {
#pragma unroll
        for (int m = 4; m <= 16; m <<= 1) {
            pzlo[nj] += __shfl_xor_sync(0xffffffffu, pzlo[nj], m);
            pzhi[nj] += __shfl_xor_sync(0xffffffffu, pzhi[nj], m);
        }
    }
    if (g == 0) {
#pragma unroll
        for (int nj = 0; nj < 8; nj++)
            *(float2*)(S.zpart[w] + nj * 8 + 2 * tq) = make_float2(pzlo[nj], pzhi[nj]);
    }
    __syncthreads();

    // invb[d] = 2 / (zA + zB)   (v+v doubling folded here)
    S.invb[t6] = 2.f / (S.zpart[0][t6] + S.zpart[1][t6]);
    __syncthreads();

    // Output mma: out^T(e,h) = P^T @ vhat, M-tiles 2, N=8, K-tiles 4 (k16)
    float Co[2][4];
    Co[0][0] = Co[0][1] = Co[0][2] = Co[0][3] = 0.f;
    Co[1][0] = Co[1][1] = Co[1][2] = Co[1][3] = 0.f;
#pragma unroll
    for (int kj = 0; kj < 4; kj++) {
        uint32_t bv[2];
        {
            int d0 = 16 * kj + 2 * tq;
            float2 v0 = *(const float2*)(S.v + g * PQ + d0);
            float2 i0 = *(const float2*)(S.invb + d0);
            bv[0] = pack_h2(v0.x * i0.x, v0.y * i0.y);
            float2 v1 = *(const float2*)(S.v + g * PQ + d0 + 8);
            float2 i1 = *(const float2*)(S.invb + d0 + 8);
            bv[1] = pack_h2(v1.x * i1.x, v1.y * i1.y);
        }
#pragma unroll
        for (int mi = 0; mi < 2; mi++) {
            uint32_t av[4] = { eh[mi][2 * kj][0], eh[mi][2 * kj][1],
                               eh[mi][2 * kj + 1][0], eh[mi][2 * kj + 1][1] };
            mma_f16(Co[mi], av, bv);
        }
    }

    // store: scr[b, e*64 + n/64, (n%64)*8 + h], half2 per (e, h-pair)
    {
        const int b = pix >> 12;
        const int n = pix & 4095;
        const size_t base = ((size_t)(b * 4096 + (n >> 6))) * CDIM + (n & 63) * 8 + 2 * tq;
        const size_t estep = (size_t)64 * CDIM;
#pragma unroll
        for (int mi = 0; mi < 2; mi++) {
            int e = w * 32 + mi * 16 + g;
            *(__half2*)(scr + base + (size_t)e * estep) =
                __floats2half2_rn(Co[mi][0], Co[mi][1]);
            *(__half2*)(scr + base + (size_t)(e + 8) * estep) =
                __floats2half2_rn(Co[mi][2], Co[mi][3]);
        }
    }
}

// ---------------------------------------------------------------------------
extern "C" void kernel_launch(void* const* d_in, const int* in_sizes, int n_in,
                              void* d_out, int out_size)
{
    const float* x     = (const float*)d_in[0];
    const float* Wq    = (const float*)d_in[1];
    const float* Wk    = (const float*)d_in[2];
    const float* Wv    = (const float*)d_in[3];
    // d_in[4] = conv_w: dead in the reference
    const float* projw = (const float*)d_in[5];
    const float* projb = (const float*)d_in[6];
    float* out = (float*)d_out;

    cudaFuncSetAttribute(gemm_f16<true>, cudaFuncAttributeMaxDynamicSharedMemorySize, GSMEM);
    cudaFuncSetAttribute(gemm_f16<false>, cudaFuncAttributeMaxDynamicSharedMemorySize, GSMEM);

    __half *x16, *s16, *w16, *qkv16;
    cudaGetSymbolAddress((void**)&x16, g_x16);
    cudaGetSymbolAddress((void**)&s16, g_s16);
    cudaGetSymbolAddress((void**)&w16, g_w16);
    cudaGetSymbolAddress((void**)&qkv16, g_qkv16);

    // cvt_x: 4 float4s per thread (MLP=4); n4 = 2,097,152; grid = n4/4/256
    cvt_x<<<MTOT * CDIM / 16 / 256, 256>>>((const float4*)x, (uint2*)x16, MTOT * CDIM / 4);
    cvt_w<<<dim3(256, 4), 256>>>(
        (const float4*)Wq, (const float4*)Wk, (const float4*)Wv,
        (const float4*)projw, (uint2*)w16);

    // fused QKV GEMM: [16384,512] x [1536,512]^T -> fp16 [16384,1536]
    gemm_f16<true><<<dim3(NQKV / 128, MTOT / 128), 256, GSMEM>>>(
        x16, w16, nullptr, qkv16, NQKV);

    attn_kernel<<<MTOT, 64>>>(qkv16, s16);

    // proj GEMM: [16384,512] x [512,512]^T -> fp32 out
    gemm_f16<false><<<dim3(CDIM / 128, MTOT / 128), 256, GSMEM>>>(
        s16, w16 + 3 * CDIM * CDIM, projb, out, CDIM);
}

// round 14
// speedup vs baseline: 1.1508x; 1.0584x over previous
#include <cuda_runtime.h>
#include <cuda_fp16.h>
#include <stdint.h>
#include <math.h>

#define MTOT 16384
#define CDIM 512
#define NQKV 1536
#define LOG2E 1.44269504088896f

// ---------------------------------------------------------------------------
// Scratch (static __device__: no allocations allowed)
// ---------------------------------------------------------------------------
__device__ __half g_x16[MTOT * CDIM];
__device__ __half g_qkv16[(size_t)MTOT * NQKV];
__device__ __half g_s16[MTOT * CDIM];
__device__ __half g_w16[4 * CDIM * CDIM];   // Wq, Wk, Wv, proj

// ---------------------------------------------------------------------------
// PTX helpers (arch-portable)
// ---------------------------------------------------------------------------
__device__ __forceinline__ uint32_t smem_u32(const void* p) {
    uint32_t a;
    asm("{ .reg .u64 t; cvta.to.shared.u64 t, %1; cvt.u32.u64 %0, t; }"
        : "=r"(a) : "l"(p));
    return a;
}
__device__ __forceinline__ void ldm_x4(uint32_t* r, uint32_t addr) {
    asm volatile("ldmatrix.sync.aligned.m8n8.x4.shared.b16 {%0,%1,%2,%3}, [%4];"
                 : "=r"(r[0]), "=r"(r[1]), "=r"(r[2]), "=r"(r[3]) : "r"(addr));
}
__device__ __forceinline__ void ldm_x2(uint32_t* r, uint32_t addr) {
    asm volatile("ldmatrix.sync.aligned.m8n8.x2.shared.b16 {%0,%1}, [%2];"
                 : "=r"(r[0]), "=r"(r[1]) : "r"(addr));
}
__device__ __forceinline__ void ldm_x4_trans(uint32_t* r, uint32_t addr) {
    asm volatile("ldmatrix.sync.aligned.m8n8.x4.trans.shared.b16 {%0,%1,%2,%3}, [%4];"
                 : "=r"(r[0]), "=r"(r[1]), "=r"(r[2]), "=r"(r[3]) : "r"(addr));
}
__device__ __forceinline__ void mma_f16(float* d, const uint32_t* a, const uint32_t* b) {
    asm volatile(
        "mma.sync.aligned.m16n8k16.row.col.f32.f16.f16.f32 "
        "{%0,%1,%2,%3}, {%4,%5,%6,%7}, {%8,%9}, {%0,%1,%2,%3};"
        : "+f"(d[0]), "+f"(d[1]), "+f"(d[2]), "+f"(d[3])
        : "r"(a[0]), "r"(a[1]), "r"(a[2]), "r"(a[3]), "r"(b[0]), "r"(b[1]));
}
__device__ __forceinline__ void mma_f16_k8(float* d, uint32_t a0, uint32_t a1, uint32_t b0) {
    asm volatile(
        "mma.sync.aligned.m16n8k8.row.col.f32.f16.f16.f32 "
        "{%0,%1,%2,%3}, {%4,%5}, {%6}, {%0,%1,%2,%3};"
        : "+f"(d[0]), "+f"(d[1]), "+f"(d[2]), "+f"(d[3])
        : "r"(a0), "r"(a1), "r"(b0));
}
__device__ __forceinline__ void cp_async16(uint32_t dst, const void* src) {
    asm volatile("cp.async.cg.shared.global [%0], [%1], 16;" :: "r"(dst), "l"(src));
}
#define CP_COMMIT() asm volatile("cp.async.commit_group;" ::: "memory")
#define CP_WAIT(N)  asm volatile("cp.async.wait_group %0;" :: "n"(N) : "memory")

__device__ __forceinline__ uint32_t pack_h2(float a, float b) {
    __half2 h = __floats2half2_rn(a, b);
    return *(uint32_t*)&h;
}
__device__ __forceinline__ float ex2f(float x) {
    float r;
    asm("ex2.approx.f32 %0, %1;" : "=f"(r) : "f"(x));
    return r;
}

// ---------------------------------------------------------------------------
// fp16 GEMM (unchanged, R13): BM=128, BN=128, BK=32, 256 threads, 3-stage,
// 2 CTAs/SM, single barrier per mainloop iteration.
// ---------------------------------------------------------------------------
#define PITCH 40
#define SH ((128 + 128) * PITCH)
#define OFF_B (128 * PITCH)
#define GSMEM (3 * SH * 2)

template <bool HOUT>
__global__ __launch_bounds__(256, 2)
void gemm_f16(const __half* __restrict__ A, const __half* __restrict__ B,
              const float* __restrict__ bias, void* __restrict__ Cv, int ldc)
{
    extern __shared__ __align__(16) __half sm[];
    const int tid = threadIdx.x;
    const int wid = tid >> 5, L = tid & 31;
    const int m0 = blockIdx.y * 128;
    const int n0 = blockIdx.x * 128;
    const int wm = (wid >> 2) * 64;
    const int wn = (wid & 3) * 32;
    const uint32_t sb = smem_u32(sm);

    const __half* Ab = A + (size_t)m0 * CDIM;
    const __half* Bb = B + (size_t)n0 * CDIM;

    float acc[4][4][4];
#pragma unroll
    for (int i = 0; i < 4; i++)
#pragma unroll
        for (int j = 0; j < 4; j++)
#pragma unroll
            for (int q = 0; q < 4; q++) acc[i][j][q] = 0.f;

    const int aRow = L & 15, aK = (L >> 4) * 8;
    const int bRowL = (L & 7) + ((L & 16) ? 8 : 0);
    const int bK = ((L >> 3) & 1) * 8;
    const int lr = tid >> 1, lc = tid & 1;

    auto load_stage = [&](int stage, int k0) {
        const uint32_t s0 = sb + (uint32_t)stage * SH * 2;
        cp_async16(s0 + (uint32_t)(lr * PITCH + lc * 8) * 2,
                   Ab + (size_t)lr * CDIM + k0 + lc * 8);
        cp_async16(s0 + (uint32_t)(lr * PITCH + (lc + 2) * 8) * 2,
                   Ab + (size_t)lr * CDIM + k0 + (lc + 2) * 8);
        cp_async16(s0 + OFF_B * 2 + (uint32_t)(lr * PITCH + lc * 8) * 2,
                   Bb + (size_t)lr * CDIM + k0 + lc * 8);
        cp_async16(s0 + OFF_B * 2 + (uint32_t)(lr * PITCH + (lc + 2) * 8) * 2,
                   Bb + (size_t)lr * CDIM + k0 + (lc + 2) * 8);
    };

    load_stage(0, 0);  CP_COMMIT();
    load_stage(1, 32); CP_COMMIT();

    const int NIT = CDIM / 32;   // 16
    for (int s = 0; s < NIT; s++) {
        CP_WAIT(1);
        __syncthreads();
        if (s + 2 < NIT) load_stage((s + 2) % 3, (s + 2) * 32);
        CP_COMMIT();

        const uint32_t pA = sb + (uint32_t)(s % 3) * SH * 2;
        const uint32_t pB = pA + OFF_B * 2;

#pragma unroll
        for (int kk = 0; kk < 32; kk += 16) {
            uint32_t ah[4][4], bh[4][2];
#pragma unroll
            for (int mi = 0; mi < 4; mi++) {
                uint32_t ro = (uint32_t)((wm + mi * 16 + aRow) * PITCH + kk + aK) * 2;
                ldm_x4(ah[mi], pA + ro);
            }
#pragma unroll
            for (int nb = 0; nb < 2; nb++) {
                uint32_t ro = (uint32_t)((wn + nb * 16 + bRowL) * PITCH + kk + bK) * 2;
                uint32_t th[4];
                ldm_x4(th, pB + ro);
                bh[nb * 2][0] = th[0];     bh[nb * 2][1] = th[1];
                bh[nb * 2 + 1][0] = th[2]; bh[nb * 2 + 1][1] = th[3];
            }
#pragma unroll
            for (int mi = 0; mi < 4; mi++)
#pragma unroll
                for (int ni = 0; ni < 4; ni++)
                    mma_f16(acc[mi][ni], ah[mi], bh[ni]);
        }
    }

    const int cr = L >> 2, cc = (L & 3) * 2;
#pragma unroll
    for (int mi = 0; mi < 4; mi++) {
#pragma unroll
        for (int ni = 0; ni < 4; ni++) {
            int row = m0 + wm + mi * 16 + cr;
            int col = n0 + wn + ni * 8 + cc;
            float b0 = 0.f, b1 = 0.f;
            if (bias) { b0 = bias[col]; b1 = bias[col + 1]; }
            if (HOUT) {
                __half* C = (__half*)Cv;
                *(__half2*)&C[(size_t)row * ldc + col] =
                    __floats2half2_rn(acc[mi][ni][0] + b0, acc[mi][ni][1] + b1);
                *(__half2*)&C[(size_t)(row + 8) * ldc + col] =
                    __floats2half2_rn(acc[mi][ni][2] + b0, acc[mi][ni][3] + b1);
            } else {
                float* C = (float*)Cv;
                *(float2*)&C[(size_t)row * ldc + col] =
                    make_float2(acc[mi][ni][0] + b0, acc[mi][ni][1] + b1);
                *(float2*)&C[(size_t)(row + 8) * ldc + col] =
                    make_float2(acc[mi][ni][2] + b0, acc[mi][ni][3] + b1);
            }
        }
    }
}

// ---------------------------------------------------------------------------
// fp32 -> fp16 converts (R13)
// ---------------------------------------------------------------------------
__global__ void cvt_x(const float4* __restrict__ src, uint2* __restrict__ dst, int n4)
{
    int i = blockIdx.x * blockDim.x + threadIdx.x;
    int stride = gridDim.x * blockDim.x;
    float4 v0 = src[i];
    float4 v1 = src[i + stride];
    float4 v2 = src[i + 2 * stride];
    float4 v3 = src[i + 3 * stride];
    union { uint2 u; __half b[4]; } H;
#define CVT4(V, IDX) \
    H.b[0] = __float2half(V.x); H.b[1] = __float2half(V.y); \
    H.b[2] = __float2half(V.z); H.b[3] = __float2half(V.w); \
    dst[IDX] = H.u;
    CVT4(v0, i)
    CVT4(v1, i + stride)
    CVT4(v2, i + 2 * stride)
    CVT4(v3, i + 3 * stride)
#undef CVT4
}

__global__ void cvt_w(const float4* __restrict__ w0, const float4* __restrict__ w1,
                      const float4* __restrict__ w2, const float4* __restrict__ w3,
                      uint2* __restrict__ dst)
{
    int wsel = blockIdx.y;
    const float4* src = (wsel == 0) ? w0 : (wsel == 1) ? w1 : (wsel == 2) ? w2 : w3;
    int i = blockIdx.x * blockDim.x + threadIdx.x;
    float4 v = src[i];
    union { uint2 u; __half b[4]; } H;
    H.b[0] = __float2half(v.x); H.b[1] = __float2half(v.y);
    H.b[2] = __float2half(v.z); H.b[3] = __float2half(v.w);
    dst[(size_t)wsel * 65536 + i] = H.u;
}

// ---------------------------------------------------------------------------
// Per-pixel attention: ALL matmul-shaped phases on tensor cores.
// - q/k/v staged raw fp16 (no fp32 conversion staging), pitch 72 halfs
// - gram = v@v^T via mma (warp 0) concurrent with q/k norms (warp 1);
//   v-norms from the gram diagonal
// - head-mix via mma with rn_q / rn_k*log2e folded into the fp16 softmax
//   weight tiles sAq/sAk; A-fragments via ldmatrix.trans on raw q/k
// - stage-2 + output mma unchanged (R9/R13 verified fragment paths)
// ---------------------------------------------------------------------------
#define PHQ 72

struct __align__(16) PixS {
    __half q16[8 * PHQ];
    __half k16[8 * PHQ];
    __half v16[8 * PHQ];
    float rn[16];                      // rn_q[0..7], rn_k*log2e[8..15]
    float sAraw[8][8];                 // raw v-gram (fp32 from TC)
    __align__(16) __half sAq[8][8];    // softmax * rn_q[g]
    __align__(16) __half sAk[8][8];    // softmax * rn_k[g] * log2e
    __align__(16) __half qT[64 * 8];   // q'[d][h]
    __align__(16) __half kT[64 * 8];   // k'[d][h] (log2-scaled)
    __align__(16) float zpart[2][64];
    __align__(16) float invb[64];
};

__global__ __launch_bounds__(64) void attn_kernel(
    const __half* __restrict__ QKV, __half* __restrict__ scr)
{
    __shared__ PixS S;
    const int t6 = threadIdx.x;
    const int pix = blockIdx.x;
    const int w = t6 >> 5;             // warp (0/1)
    const int L = t6 & 31;
    const int g4 = L >> 2, tq = L & 3; // C-fragment row/colpair

    // ---- stage raw fp16 qkv (3x 16B copies per thread) ----
    {
        const uint4* src = (const uint4*)(QKV + (size_t)pix * NQKV);
        const uint32_t off = (uint32_t)((t6 >> 3) * PHQ + (t6 & 7) * 8);
        *(uint4*)(S.q16 + off) = src[t6];
        *(uint4*)(S.k16 + off) = src[64 + t6];
        *(uint4*)(S.v16 + off) = src[128 + t6];
    }
    __syncthreads();

    if (w == 0) {
        // ---- gram via mma: C(h,g) = sum_d v(h,d) v(g,d), rows 8-15 dup ----
        float cg[4] = {0.f, 0.f, 0.f, 0.f};
        const uint32_t vb = smem_u32(S.v16);
        const int row = L & 7;
        const uint32_t abase = vb + (uint32_t)(row * PHQ) * 2;
        const uint32_t kA = (L >= 16) ? 16 : 0;        // A groups 2,3 -> k+8
        const uint32_t kB = ((L >> 3) & 1) ? 16 : 0;   // B tile1 -> k+8
#pragma unroll
        for (int kj = 0; kj < 4; kj++) {
            uint32_t a[4], b[2];
            ldm_x4(a, abase + kA + (uint32_t)kj * 32);
            ldm_x2(b, abase + kB + (uint32_t)kj * 32);
            mma_f16(cg, a, b);
        }
        *(float2*)&S.sAraw[g4][2 * tq] = make_float2(cg[0], cg[1]);
    } else {
        // ---- q/k norms (2 lanes per row) ----
        const int row = L >> 1, hf = L & 1;
        const __half* p = ((row < 8) ? S.q16 + row * PHQ
                                     : S.k16 + (row - 8) * PHQ) + hf * 32;
        float s = 0.f;
#pragma unroll
        for (int i = 0; i < 4; i++) {
            uint4 u = ((const uint4*)p)[i];
            const __half2* h2 = (const __half2*)&u;
#pragma unroll
            for (int j = 0; j < 4; j++) {
                float2 f = __half22float2(h2[j]);
                s = fmaf(f.x, f.x, fmaf(f.y, f.y, s));
            }
        }
        s += __shfl_xor_sync(0xffffffffu, s, 1);
        if (hf == 0) {
            float inv = 1.f / fmaxf(sqrtf(s), 1e-12f);
            S.rn[row] = (row < 8) ? inv : inv * LOG2E;
        }
    }
    __syncthreads();

    // ---- softmax rows + build fp16 weight tiles (v-norms from diagonal) ----
    if (t6 < 8) {
        float rv[8];
#pragma unroll
        for (int g = 0; g < 8; g++)
            rv[g] = 1.f / fmaxf(sqrtf(S.sAraw[g][g]), 1e-12f);
        float rh = rv[t6], e[8], sum = 0.f;
#pragma unroll
        for (int g = 0; g < 8; g++) {
            e[g] = __expf(S.sAraw[t6][g] * rh * rv[g]);
            sum += e[g];
        }
        float inv = 1.f / sum;
        union { uint4 u; __half hh[8]; } Q_, K_;
#pragma unroll
        for (int g = 0; g < 8; g++) {
            float sft = e[g] * inv;
            Q_.hh[g] = __float2half(sft * S.rn[g]);
            K_.hh[g] = __float2half(sft * S.rn[8 + g]);
        }
        *(uint4*)&S.sAq[t6][0] = Q_.u;
        *(uint4*)&S.sAk[t6][0] = K_.u;
    }
    __syncthreads();

    // ---- head-mix via mma: C(d,h) = sum_g raw(g,d) * sAx(h,g) ----
    {
        const int row = L & 7, grp = L >> 3;
        const uint32_t doff2 = (uint32_t)(w * 32 + grp * 8) * 2;
        uint32_t aq[4], ak[4], b2[2];
        ldm_x4_trans(aq, smem_u32(S.q16) + (uint32_t)(row * PHQ) * 2 + doff2);
        ldm_x4_trans(ak, smem_u32(S.k16) + (uint32_t)(row * PHQ) * 2 + doff2);
        uint32_t baddr = (L < 8) ? smem_u32(S.sAq) + (uint32_t)row * 16
                                 : smem_u32(S.sAk) + (uint32_t)(L & 7) * 16;
        ldm_x2(b2, baddr);
        float cq0[4] = {0,0,0,0}, cq1[4] = {0,0,0,0};
        float ck0[4] = {0,0,0,0}, ck1[4] = {0,0,0,0};
        mma_f16_k8(cq0, aq[0], aq[1], b2[0]);
        mma_f16_k8(cq1, aq[2], aq[3], b2[0]);
        mma_f16_k8(ck0, ak[0], ak[1], b2[1]);
        mma_f16_k8(ck1, ak[2], ak[3], b2[1]);
        const int dbase = w * 32 + g4;
        *(__half2*)&S.qT[(dbase)      * 8 + 2 * tq] = __floats2half2_rn(cq0[0], cq0[1]);
        *(__half2*)&S.qT[(dbase + 8)  * 8 + 2 * tq] = __floats2half2_rn(cq0[2], cq0[3]);
        *(__half2*)&S.qT[(dbase + 16) * 8 + 2 * tq] = __floats2half2_rn(cq1[0], cq1[1]);
        *(__half2*)&S.qT[(dbase + 24) * 8 + 2 * tq] = __floats2half2_rn(cq1[2], cq1[3]);
        *(__half2*)&S.kT[(dbase)      * 8 + 2 * tq] = __floats2half2_rn(ck0[0], ck0[1]);
        *(__half2*)&S.kT[(dbase + 8)  * 8 + 2 * tq] = __floats2half2_rn(ck0[2], ck0[3]);
        *(__half2*)&S.kT[(dbase + 16) * 8 + 2 * tq] = __floats2half2_rn(ck1[0], ck1[1]);
        *(__half2*)&S.kT[(dbase + 24) * 8 + 2 * tq] = __floats2half2_rn(ck1[2], ck1[3]);
    }
    __syncthreads();

    // ================= stage-2 + output (R13 verified path) =================
    uint32_t qa[4];
    ldm_x4(qa, smem_u32(S.qT) + (uint32_t)(w * 32 + L) * 16);
    uint32_t kb[8];
    ldm_x4(kb + 0, smem_u32(S.kT) + (uint32_t)L * 16);
    ldm_x4(kb + 4, smem_u32(S.kT) + (uint32_t)(32 + L) * 16);

    float Cs[2][8][4];
#pragma unroll
    for (int mi = 0; mi < 2; mi++)
#pragma unroll
        for (int nj = 0; nj < 8; nj++) {
            Cs[mi][nj][0] = Cs[mi][nj][1] = Cs[mi][nj][2] = Cs[mi][nj][3] = 0.f;
            mma_f16_k8(Cs[mi][nj], qa[2 * mi], qa[2 * mi + 1], kb[nj]);
        }

    uint32_t eh[2][8][2];
    float pzlo[8], pzhi[8];
#pragma unroll
    for (int nj = 0; nj < 8; nj++) { pzlo[nj] = 0.f; pzhi[nj] = 0.f; }
#pragma unroll
    for (int mi = 0; mi < 2; mi++)
#pragma unroll
        for (int nj = 0; nj < 8; nj++) {
            float e0 = ex2f(Cs[mi][nj][0]);
            float e1 = ex2f(Cs[mi][nj][1]);
            float e2 = ex2f(Cs[mi][nj][2]);
            float e3 = ex2f(Cs[mi][nj][3]);
            pzlo[nj] += e0 + e2;
            pzhi[nj] += e1 + e3;
            eh[mi][nj][0] = pack_h2(e0, e1);
            eh[mi][nj][1] = pack_h2(e2, e3);
        }
#pragma unroll
    for (int nj = 0; nj < 8; nj++) {
#pragma unroll
        for (int m = 4; m <= 16; m <<= 1) {
            pzlo[nj] += __shfl_xor_sync(0xffffffffu, pzlo[nj], m);
            pzhi[nj] += __shfl_xor_sync(0xffffffffu, pzhi[nj], m);
        }
    }
    if (g4 == 0) {
#pragma unroll
        for (int nj = 0; nj < 8; nj++)
            *(float2*)(S.zpart[w] + nj * 8 + 2 * tq) = make_float2(pzlo[nj], pzhi[nj]);
    }
    __syncthreads();

    S.invb[t6] = 2.f / (S.zpart[0][t6] + S.zpart[1][t6]);
    __syncthreads();

    float Co[2][4];
    Co[0][0] = Co[0][1] = Co[0][2] = Co[0][3] = 0.f;
    Co[1][0] = Co[1][1] = Co[1][2] = Co[1][3] = 0.f;
#pragma unroll
    for (int kj = 0; kj < 4; kj++) {
        uint32_t bv[2];
        {
            int d0 = 16 * kj + 2 * tq;
            float2 f0 = __half22float2(*(const __half2*)&S.v16[g4 * PHQ + d0]);
            float2 i0 = *(const float2*)&S.invb[d0];
            bv[0] = pack_h2(f0.x * i0.x, f0.y * i0.y);
            float2 f1 = __half22float2(*(const __half2*)&S.v16[g4 * PHQ + d0 + 8]);
            float2 i1 = *(const float2*)&S.invb[d0 + 8];
            bv[1] = pack_h2(f1.x * i1.x, f1.y * i1.y);
        }
#pragma unroll
        for (int mi = 0; mi < 2; mi++) {
            uint32_t av[4] = { eh[mi][2 * kj][0], eh[mi][2 * kj][1],
                               eh[mi][2 * kj + 1][0], eh[mi][2 * kj + 1][1] };
            mma_f16(Co[mi], av, bv);
        }
    }

    // store: scr[b, e*64 + n/64, (n%64)*8 + h]
    {
        const int b = pix >> 12;
        const int n = pix & 4095;
        const size_t base = ((size_t)(b * 4096 + (n >> 6))) * CDIM + (n & 63) * 8 + 2 * tq;
        const size_t estep = (size_t)64 * CDIM;
#pragma unroll
        for (int mi = 0; mi < 2; mi++) {
            int e = w * 32 + mi * 16 + g4;
            *(__half2*)(scr + base + (size_t)e * estep) =
                __floats2half2_rn(Co[mi][0], Co[mi][1]);
            *(__half2*)(scr + base + (size_t)(e + 8) * estep) =
                __floats2half2_rn(Co[mi][2], Co[mi][3]);
        }
    }
}

// ---------------------------------------------------------------------------
extern "C" void kernel_launch(void* const* d_in, const int* in_sizes, int n_in,
                              void* d_out, int out_size)
{
    const float* x     = (const float*)d_in[0];
    const float* Wq    = (const float*)d_in[1];
    const float* Wk    = (const float*)d_in[2];
    const float* Wv    = (const float*)d_in[3];
    // d_in[4] = conv_w: dead in the reference
    const float* projw = (const float*)d_in[5];
    const float* projb = (const float*)d_in[6];
    float* out = (float*)d_out;

    cudaFuncSetAttribute(gemm_f16<true>, cudaFuncAttributeMaxDynamicSharedMemorySize, GSMEM);
    cudaFuncSetAttribute(gemm_f16<false>, cudaFuncAttributeMaxDynamicSharedMemorySize, GSMEM);

    __half *x16, *s16, *w16, *qkv16;
    cudaGetSymbolAddress((void**)&x16, g_x16);
    cudaGetSymbolAddress((void**)&s16, g_s16);
    cudaGetSymbolAddress((void**)&w16, g_w16);
    cudaGetSymbolAddress((void**)&qkv16, g_qkv16);

    cvt_x<<<MTOT * CDIM / 16 / 256, 256>>>((const float4*)x, (uint2*)x16, MTOT * CDIM / 4);
    cvt_w<<<dim3(256, 4), 256>>>(
        (const float4*)Wq, (const float4*)Wk, (const float4*)Wv,
        (const float4*)projw, (uint2*)w16);

    // fused QKV GEMM: [16384,512] x [1536,512]^T -> fp16 [16384,1536]
    gemm_f16<true><<<dim3(NQKV / 128, MTOT / 128), 256, GSMEM>>>(
        x16, w16, nullptr, qkv16, NQKV);

    attn_kernel<<<MTOT, 64>>>(qkv16, s16);

    // proj GEMM: [16384,512] x [512,512]^T -> fp32 out
    gemm_f16<false><<<dim3(CDIM / 128, MTOT / 128), 256, GSMEM>>>(
        s16, w16 + 3 * CDIM * CDIM, projb, out, CDIM);
}